// round 10
// baseline (speedup 1.0000x reference)
#include <cuda_runtime.h>
#include <cuda_bf16.h>
#include <math.h>

#define NHC 256
#define BATCH 64
#define TMAX 4096
#define TOUT_MAX 2048
#define KDIM 1280
#define KC 64
#define NCHUNK 20
#define NT 64
#define APAD 136
#define FRAG_PER_MT (NCHUNK*4*8*32)   // 20480 uint4 per Mtile

// ---------------- device global scratch ----------------
__device__ float g_bufL[BATCH*NHC*TOUT_MAX];
__device__ unsigned g_inplane[BATCH*NHC*TMAX];     // packed (hi<<16)|lo bf16
__device__ unsigned g_hplane0[BATCH*NHC*TOUT_MAX];
__device__ unsigned g_hplane1[BATCH*NHC*TOUT_MAX];
__device__ unsigned g_rplane [BATCH*NHC*TOUT_MAX];
__device__ float g_captured[BATCH*NHC];
__device__ float g_wdep[512*8];                    // wd[0..4], sum, pad
// A fragments in mma register order: [Mt][ch][ks][tile(8)][lane(32)] uint4
__device__ __align__(16) uint4 g_a1hiF[4*FRAG_PER_MT];
__device__ __align__(16) uint4 g_a1loF[4*FRAG_PER_MT];
__device__ __align__(16) uint4 g_a2hiF[2*FRAG_PER_MT];
__device__ __align__(16) uint4 g_a2loF[2*FRAG_PER_MT];

// ---------------- helpers ----------------
__device__ __forceinline__ unsigned smem_u32(const void* p) {
    unsigned a;
    asm("{ .reg .u64 t; cvta.to.shared.u64 t, %1; cvt.u32.u64 %0, t; }" : "=r"(a) : "l"(p));
    return a;
}
__device__ __forceinline__ unsigned pack_hl(float v) {
    __nv_bfloat16 h = __float2bfloat16(v);
    float hf = __bfloat162float(h);
    __nv_bfloat16 l = __float2bfloat16(v - hf);
    unsigned short hb = *reinterpret_cast<unsigned short*>(&h);
    unsigned short lb = *reinterpret_cast<unsigned short*>(&l);
    return ((unsigned)hb << 16) | (unsigned)lb;
}
__device__ __forceinline__ int finish_depth(int n) {
    #pragma unroll 1
    for (int dd = 0; dd < 12; dd++) {
        n = (n - 1) / 2 + 1;
        if (n <= 1) return dd;
    }
    return 11;
}
__device__ __forceinline__ void ldm4t(unsigned* f, unsigned addr) {
    asm volatile("ldmatrix.sync.aligned.m8n8.x4.trans.shared.b16 {%0,%1,%2,%3}, [%4];"
        : "=r"(f[0]), "=r"(f[1]), "=r"(f[2]), "=r"(f[3]) : "r"(addr));
}
__device__ __forceinline__ void mma16816(float* c, const unsigned* a, const unsigned* b) {
    asm volatile("mma.sync.aligned.m16n8k16.row.col.f32.bf16.bf16.f32 "
        "{%0,%1,%2,%3}, {%4,%5,%6,%7}, {%8,%9}, {%0,%1,%2,%3};"
        : "+f"(c[0]), "+f"(c[1]), "+f"(c[2]), "+f"(c[3])
        : "r"(a[0]), "r"(a[1]), "r"(a[2]), "r"(a[3]), "r"(b[0]), "r"(b[1]));
}

// smem: per stage: hi plane 64*APAD*2 = 17408 B, lo plane same
#define SM_HALF  17408
#define SM_STAGE 34816
#define SM_DYN   69632

// ---------------- prep kernels ----------------
__global__ void prep_input(const float* __restrict__ h) {
    long long idx = (long long)blockIdx.x * blockDim.x + threadIdx.x;
    if (idx < (long long)BATCH * NHC * TMAX)
        g_inplane[idx] = pack_hl(h[idx]);
}
__global__ void prep_w1(const float* __restrict__ w1) {
    int idx = blockIdx.x * blockDim.x + threadIdx.x;
    if (idx >= 4 * FRAG_PER_MT) return;
    int lane = idx & 31;
    int tile = (idx >> 5) & 7;
    int ks   = (idx >> 8) & 3;
    int rest = idx >> 10;          // Mt*20 + ch
    int ch = rest % NCHUNK;
    int Mt = rest / NCHUNK;
    int r0 = tile * 16 + (lane >> 2);
    int c0 = ks * 16 + (lane & 3) * 2;
    unsigned hi[4], lo[4];
    #pragma unroll
    for (int e = 0; e < 4; e++) {
        int rr = r0 + (e & 1) * 8;
        int cc = c0 + (e >> 1) * 8;
        unsigned h2 = 0, l2 = 0;
        #pragma unroll
        for (int j = 0; j < 2; j++) {
            int kg = ch * KC + cc + j;
            int ic = kg / 5, kk = kg - 5 * ic;
            int oc = Mt * 128 + rr;
            float w = w1[(oc * 257 + ic) * 5 + kk];
            __nv_bfloat16 h = __float2bfloat16(w);
            __nv_bfloat16 l = __float2bfloat16(w - __bfloat162float(h));
            h2 |= ((unsigned)*(unsigned short*)&h) << (16 * j);
            l2 |= ((unsigned)*(unsigned short*)&l) << (16 * j);
        }
        hi[e] = h2; lo[e] = l2;
    }
    g_a1hiF[idx] = make_uint4(hi[0], hi[1], hi[2], hi[3]);
    g_a1loF[idx] = make_uint4(lo[0], lo[1], lo[2], lo[3]);
}
__global__ void prep_w2(const float* __restrict__ w2) {
    int idx = blockIdx.x * blockDim.x + threadIdx.x;
    if (idx >= 2 * FRAG_PER_MT) return;
    int lane = idx & 31;
    int tile = (idx >> 5) & 7;
    int ks   = (idx >> 8) & 3;
    int rest = idx >> 10;
    int ch = rest % NCHUNK;
    int Mt = rest / NCHUNK;
    int r0 = tile * 16 + (lane >> 2);
    int c0 = ks * 16 + (lane & 3) * 2;
    unsigned hi[4], lo[4];
    #pragma unroll
    for (int e = 0; e < 4; e++) {
        int rr = r0 + (e & 1) * 8;
        int cc = c0 + (e >> 1) * 8;
        unsigned h2 = 0, l2 = 0;
        #pragma unroll
        for (int j = 0; j < 2; j++) {
            int kg = ch * KC + cc + j;
            int ic = kg / 5, kk = kg - 5 * ic;
            int oc = Mt * 128 + rr;
            float w = w2[(oc * 256 + ic) * 5 + kk];
            __nv_bfloat16 h = __float2bfloat16(w);
            __nv_bfloat16 l = __float2bfloat16(w - __bfloat162float(h));
            h2 |= ((unsigned)*(unsigned short*)&h) << (16 * j);
            l2 |= ((unsigned)*(unsigned short*)&l) << (16 * j);
        }
        hi[e] = h2; lo[e] = l2;
    }
    g_a2hiF[idx] = make_uint4(hi[0], hi[1], hi[2], hi[3]);
    g_a2loF[idx] = make_uint4(lo[0], lo[1], lo[2], lo[3]);
}
__global__ void prep_wdep(const float* __restrict__ w1) {
    int oc = blockIdx.x * blockDim.x + threadIdx.x;
    if (oc >= 512) return;
    float s = 0.f;
    #pragma unroll
    for (int k = 0; k < 5; k++) {
        float w = w1[(oc * 257 + 256) * 5 + k];
        g_wdep[oc * 8 + k] = w;
        s += w;
    }
    g_wdep[oc * 8 + 5] = s;
    g_wdep[oc * 8 + 6] = 0.f;
    g_wdep[oc * 8 + 7] = 0.f;
}

// ---------------- conv1 (stride 2), 2 batches per CTA ----------------
__global__ __launch_bounds__(256) void conv1_mma(
    const int* __restrict__ N0, const float* __restrict__ b1,
    const unsigned* __restrict__ plane,
    int d, int T_in, int T_out, float dval)
{
    extern __shared__ char smc[];
    const unsigned smb = smem_u32(smc);
    const int tid = threadIdx.x;
    const int b0 = blockIdx.z * 2, b1b = b0 + 1;
    const int Mtile = blockIdx.y, t0 = blockIdx.x * NT;
    const int lane = tid & 31, q = lane >> 3, r = lane & 7;
    const int w8 = tid >> 5, wmi = w8 >> 1, wni = w8 & 1;

    const int n00 = N0[b0], n01 = N0[b1b];
    const int Ncur0 = (n00 + (1 << d) - 1) >> d;
    const int Nnew0 = (n00 + (2 << d) - 1) >> (d + 1);
    const int Ncur1 = (n01 + (1 << d) - 1) >> d;
    const int Nnew1 = (n01 + (2 << d) - 1) >> (d + 1);

    const unsigned bOff0 = (unsigned)(((q & 1) * 8 + r) * (APAD * 2) + (wni * 32 + (q >> 1) * 8) * 2);
    const unsigned bOff1 = bOff0 + 32;

    float acc[2][8][4];
    #pragma unroll
    for (int mt = 0; mt < 2; mt++)
        #pragma unroll
        for (int nt = 0; nt < 8; nt++)
            #pragma unroll
            for (int e = 0; e < 4; e++) acc[mt][nt][e] = 0.f;

    const int pbase = 2 * (t0 + 2 * lane) - 2;
    unsigned v[32];

    auto bload = [&](int ch) {
        #pragma unroll
        for (int i = 0; i < 8; i++) {
            int kl = i * 8 + w8;
            int kg = ch * KC + kl;
            int ic = kg / 5, kk = kg - 5 * ic;
            unsigned base0 = (unsigned)(b0 * NHC + ic) * (unsigned)T_in;
            unsigned base1 = (unsigned)(b1b * NHC + ic) * (unsigned)T_in;
            int p0 = pbase + kk;
            int p1 = p0 + 2;
            v[2 * i]          = (p0 >= 0 && p0 < Ncur0) ? plane[base0 + p0] : 0u;
            v[2 * i + 1]      = (p1 >= 0 && p1 < Ncur0) ? plane[base0 + p1] : 0u;
            v[16 + 2 * i]     = (p0 >= 0 && p0 < Ncur1) ? plane[base1 + p0] : 0u;
            v[16 + 2 * i + 1] = (p1 >= 0 && p1 < Ncur1) ? plane[base1 + p1] : 0u;
        }
    };
    auto bstore = [&](int st) {
        unsigned* bh = (unsigned*)(smc + st * SM_STAGE);
        unsigned* bl = bh + (SM_HALF >> 2);
        #pragma unroll
        for (int i = 0; i < 8; i++) {
            int kl = i * 8 + w8;
            int so = (kl * APAD + 2 * lane) >> 1;
            unsigned v0 = v[2 * i], v1 = v[2 * i + 1];
            bh[so] = (v0 >> 16) | (v1 & 0xFFFF0000u);
            bl[so] = (v0 & 0xFFFFu) | (v1 << 16);
            unsigned u0 = v[16 + 2 * i], u1 = v[16 + 2 * i + 1];
            bh[so + 32] = (u0 >> 16) | (u1 & 0xFFFF0000u);
            bl[so + 32] = (u0 & 0xFFFFu) | (u1 << 16);
        }
    };

    const uint4* Ah0 = g_a1hiF + (size_t)Mtile * FRAG_PER_MT;
    const uint4* Al0 = g_a1loF + (size_t)Mtile * FRAG_PER_MT;

    bload(0);
    for (int ch = 0; ch < NCHUNK; ch++) {
        const int st = ch & 1;
        bstore(st);
        __syncthreads();
        if (ch + 1 < NCHUNK) bload(ch + 1);
        const unsigned bbase = smb + st * SM_STAGE;
        #pragma unroll
        for (int ks = 0; ks < 4; ks++) {
            const int fidx = ((ch * 4 + ks) * 8 + wmi * 2) * 32 + lane;
            uint4 fh0 = Ah0[fidx];
            uint4 fh1 = Ah0[fidx + 32];
            uint4 fl0 = Al0[fidx];
            uint4 fl1 = Al0[fidx + 32];
            const unsigned kr = (unsigned)(ks * 16 * (APAD * 2));
            unsigned bhf[8][2], blf[8][2], f[4];
            ldm4t(f, bbase + bOff0 + kr);
            bhf[0][0] = f[0]; bhf[0][1] = f[1]; bhf[1][0] = f[2]; bhf[1][1] = f[3];
            ldm4t(f, bbase + bOff1 + kr);
            bhf[2][0] = f[0]; bhf[2][1] = f[1]; bhf[3][0] = f[2]; bhf[3][1] = f[3];
            ldm4t(f, bbase + bOff0 + 128 + kr);
            bhf[4][0] = f[0]; bhf[4][1] = f[1]; bhf[5][0] = f[2]; bhf[5][1] = f[3];
            ldm4t(f, bbase + bOff1 + 128 + kr);
            bhf[6][0] = f[0]; bhf[6][1] = f[1]; bhf[7][0] = f[2]; bhf[7][1] = f[3];
            ldm4t(f, bbase + SM_HALF + bOff0 + kr);
            blf[0][0] = f[0]; blf[0][1] = f[1]; blf[1][0] = f[2]; blf[1][1] = f[3];
            ldm4t(f, bbase + SM_HALF + bOff1 + kr);
            blf[2][0] = f[0]; blf[2][1] = f[1]; blf[3][0] = f[2]; blf[3][1] = f[3];
            ldm4t(f, bbase + SM_HALF + bOff0 + 128 + kr);
            blf[4][0] = f[0]; blf[4][1] = f[1]; blf[5][0] = f[2]; blf[5][1] = f[3];
            ldm4t(f, bbase + SM_HALF + bOff1 + 128 + kr);
            blf[6][0] = f[0]; blf[6][1] = f[1]; blf[7][0] = f[2]; blf[7][1] = f[3];
            const unsigned* AH[2] = {(const unsigned*)&fh0, (const unsigned*)&fh1};
            const unsigned* AL[2] = {(const unsigned*)&fl0, (const unsigned*)&fl1};
            #pragma unroll
            for (int mt = 0; mt < 2; mt++) {
                #pragma unroll
                for (int nt = 0; nt < 8; nt++) {
                    mma16816(acc[mt][nt], AH[mt], bhf[nt]);
                    mma16816(acc[mt][nt], AH[mt], blf[nt]);
                    mma16816(acc[mt][nt], AL[mt], bhf[nt]);
                }
            }
        }
    }

    // epilogue
    const int crow = lane >> 2, ccol = (lane & 3) * 2;
    const bool dep = (dval != 0.f);
    #pragma unroll
    for (int mt = 0; mt < 2; mt++) {
        #pragma unroll
        for (int rh = 0; rh < 2; rh++) {
            const int oc = Mtile * 128 + wmi * 32 + mt * 16 + rh * 8 + crow;
            const float bias = b1[oc];
            float wd[5], sfull = 0.f;
            if (dep) {
                float4 wA = *(const float4*)&g_wdep[oc * 8];
                float2 wB = *(const float2*)&g_wdep[oc * 8 + 4];
                wd[0] = wA.x; wd[1] = wA.y; wd[2] = wA.z; wd[3] = wA.w; wd[4] = wB.x;
                sfull = wB.y;
            }
            #pragma unroll
            for (int nt = 0; nt < 8; nt++) {
                const int batch = nt >> 2;
                const int bb = batch ? b1b : b0;
                const int Ncur = batch ? Ncur1 : Ncur0;
                const int Nnew = batch ? Nnew1 : Nnew0;
                const int tg = t0 + wni * 32 + (nt & 3) * 8 + ccol;
                float c0v = acc[mt][nt][rh * 2 + 0] + bias;
                float c1v = acc[mt][nt][rh * 2 + 1] + bias;
                if (dep) {
                    auto dcor = [&](int t) -> float {
                        if (t >= 1 && 2 * t + 2 < Ncur) return sfull;
                        float s = 0.f;
                        #pragma unroll
                        for (int k = 0; k < 5; k++) {
                            int p = 2 * t + k - 2;
                            if (p >= 0 && p < Ncur) s += wd[k];
                        }
                        return s;
                    };
                    c0v += dval * dcor(tg);
                    c1v += dval * dcor(tg + 1);
                }
                if (Mtile < 2) {
                    size_t off = (size_t)(bb * NHC + oc) * T_out + tg;
                    if (tg + 1 < T_out)      *(float2*)&g_bufL[off] = make_float2(c0v, c1v);
                    else if (tg < T_out)     g_bufL[off] = c0v;
                } else {
                    float r0v = fmaxf(c0v, 0.f); if (tg     >= Nnew) r0v = 0.f;
                    float r1v = fmaxf(c1v, 0.f); if (tg + 1 >= Nnew) r1v = 0.f;
                    size_t off = (size_t)(bb * NHC + oc - 256) * T_out + tg;
                    if (tg + 1 < T_out)      *(uint2*)&g_rplane[off] = make_uint2(pack_hl(r0v), pack_hl(r1v));
                    else if (tg < T_out)     g_rplane[off] = pack_hl(r0v);
                }
            }
        }
    }
}

// ---------------- conv2 (stride 1), 2 batches per CTA ----------------
__global__ __launch_bounds__(256) void conv2_mma(
    const int* __restrict__ N0, const float* __restrict__ b2,
    int d, int T_out)
{
    extern __shared__ char smc[];
    const unsigned smb = smem_u32(smc);
    const int tid = threadIdx.x;
    const int b0 = blockIdx.z * 2, b1b = b0 + 1;
    const int Mtile = blockIdx.y, t0 = blockIdx.x * NT;
    const int lane = tid & 31, q = lane >> 3, r = lane & 7;
    const int w8 = tid >> 5, wmi = w8 >> 1, wni = w8 & 1;
    unsigned* hout = (d & 1) ? g_hplane1 : g_hplane0;

    const unsigned bOff0 = (unsigned)(((q & 1) * 8 + r) * (APAD * 2) + (wni * 32 + (q >> 1) * 8) * 2);
    const unsigned bOff1 = bOff0 + 32;

    float acc[2][8][4];
    #pragma unroll
    for (int mt = 0; mt < 2; mt++)
        #pragma unroll
        for (int nt = 0; nt < 8; nt++)
            #pragma unroll
            for (int e = 0; e < 4; e++) acc[mt][nt][e] = 0.f;

    const int pbase = t0 + 2 * lane - 2;
    unsigned v[32];

    auto bload = [&](int ch) {
        #pragma unroll
        for (int i = 0; i < 8; i++) {
            int kl = i * 8 + w8;
            int kg = ch * KC + kl;
            int ic = kg / 5, kk = kg - 5 * ic;
            unsigned base0 = (unsigned)(b0 * NHC + ic) * (unsigned)T_out;
            unsigned base1 = (unsigned)(b1b * NHC + ic) * (unsigned)T_out;
            int p0 = pbase + kk;
            int p1 = p0 + 1;
            v[2 * i]          = (p0 >= 0 && p0 < T_out) ? g_rplane[base0 + p0] : 0u;
            v[2 * i + 1]      = (p1 >= 0 && p1 < T_out) ? g_rplane[base0 + p1] : 0u;
            v[16 + 2 * i]     = (p0 >= 0 && p0 < T_out) ? g_rplane[base1 + p0] : 0u;
            v[16 + 2 * i + 1] = (p1 >= 0 && p1 < T_out) ? g_rplane[base1 + p1] : 0u;
        }
    };
    auto bstore = [&](int st) {
        unsigned* bh = (unsigned*)(smc + st * SM_STAGE);
        unsigned* bl = bh + (SM_HALF >> 2);
        #pragma unroll
        for (int i = 0; i < 8; i++) {
            int kl = i * 8 + w8;
            int so = (kl * APAD + 2 * lane) >> 1;
            unsigned v0 = v[2 * i], v1 = v[2 * i + 1];
            bh[so] = (v0 >> 16) | (v1 & 0xFFFF0000u);
            bl[so] = (v0 & 0xFFFFu) | (v1 << 16);
            unsigned u0 = v[16 + 2 * i], u1 = v[16 + 2 * i + 1];
            bh[so + 32] = (u0 >> 16) | (u1 & 0xFFFF0000u);
            bl[so + 32] = (u0 & 0xFFFFu) | (u1 << 16);
        }
    };

    const uint4* Ah0 = g_a2hiF + (size_t)Mtile * FRAG_PER_MT;
    const uint4* Al0 = g_a2loF + (size_t)Mtile * FRAG_PER_MT;

    bload(0);
    for (int ch = 0; ch < NCHUNK; ch++) {
        const int st = ch & 1;
        bstore(st);
        __syncthreads();
        if (ch + 1 < NCHUNK) bload(ch + 1);
        const unsigned bbase = smb + st * SM_STAGE;
        #pragma unroll
        for (int ks = 0; ks < 4; ks++) {
            const int fidx = ((ch * 4 + ks) * 8 + wmi * 2) * 32 + lane;
            uint4 fh0 = Ah0[fidx];
            uint4 fh1 = Ah0[fidx + 32];
            uint4 fl0 = Al0[fidx];
            uint4 fl1 = Al0[fidx + 32];
            const unsigned kr = (unsigned)(ks * 16 * (APAD * 2));
            unsigned bhf[8][2], blf[8][2], f[4];
            ldm4t(f, bbase + bOff0 + kr);
            bhf[0][0] = f[0]; bhf[0][1] = f[1]; bhf[1][0] = f[2]; bhf[1][1] = f[3];
            ldm4t(f, bbase + bOff1 + kr);
            bhf[2][0] = f[0]; bhf[2][1] = f[1]; bhf[3][0] = f[2]; bhf[3][1] = f[3];
            ldm4t(f, bbase + bOff0 + 128 + kr);
            bhf[4][0] = f[0]; bhf[4][1] = f[1]; bhf[5][0] = f[2]; bhf[5][1] = f[3];
            ldm4t(f, bbase + bOff1 + 128 + kr);
            bhf[6][0] = f[0]; bhf[6][1] = f[1]; bhf[7][0] = f[2]; bhf[7][1] = f[3];
            ldm4t(f, bbase + SM_HALF + bOff0 + kr);
            blf[0][0] = f[0]; blf[0][1] = f[1]; blf[1][0] = f[2]; blf[1][1] = f[3];
            ldm4t(f, bbase + SM_HALF + bOff1 + kr);
            blf[2][0] = f[0]; blf[2][1] = f[1]; blf[3][0] = f[2]; blf[3][1] = f[3];
            ldm4t(f, bbase + SM_HALF + bOff0 + 128 + kr);
            blf[4][0] = f[0]; blf[4][1] = f[1]; blf[5][0] = f[2]; blf[5][1] = f[3];
            ldm4t(f, bbase + SM_HALF + bOff1 + 128 + kr);
            blf[6][0] = f[0]; blf[6][1] = f[1]; blf[7][0] = f[2]; blf[7][1] = f[3];
            const unsigned* AH[2] = {(const unsigned*)&fh0, (const unsigned*)&fh1};
            const unsigned* AL[2] = {(const unsigned*)&fl0, (const unsigned*)&fl1};
            #pragma unroll
            for (int mt = 0; mt < 2; mt++) {
                #pragma unroll
                for (int nt = 0; nt < 8; nt++) {
                    mma16816(acc[mt][nt], AH[mt], bhf[nt]);
                    mma16816(acc[mt][nt], AH[mt], blf[nt]);
                    mma16816(acc[mt][nt], AL[mt], bhf[nt]);
                }
            }
        }
    }

    const int crow = lane >> 2, ccol = (lane & 3) * 2;
    const int fd0 = finish_depth(N0[b0]);
    const int fd1 = finish_depth(N0[b1b]);
    #pragma unroll
    for (int mt = 0; mt < 2; mt++) {
        #pragma unroll
        for (int rh = 0; rh < 2; rh++) {
            const int oc = Mtile * 128 + wmi * 32 + mt * 16 + rh * 8 + crow;
            const float bias = b2[oc];
            #pragma unroll
            for (int nt = 0; nt < 8; nt++) {
                const int batch = nt >> 2;
                const int bb = batch ? b1b : b0;
                const int fd = batch ? fd1 : fd0;
                const int tg = t0 + wni * 32 + (nt & 3) * 8 + ccol;
                const float c0v = acc[mt][nt][rh * 2 + 0] + bias;
                const float c1v = acc[mt][nt][rh * 2 + 1] + bias;
                size_t off = (size_t)(bb * NHC + oc) * T_out + tg;
                if (tg + 1 < T_out) {
                    float2 L = *(const float2*)&g_bufL[off];
                    float v0 = fmaxf(c0v + L.x, 0.f);
                    float v1 = fmaxf(c1v + L.y, 0.f);
                    *(uint2*)&hout[off] = make_uint2(pack_hl(v0), pack_hl(v1));
                    if (tg == 0 && fd == d) g_captured[bb * NHC + oc] = v0;
                } else if (tg < T_out) {
                    float v0 = fmaxf(c0v + g_bufL[off], 0.f);
                    hout[off] = pack_hl(v0);
                    if (tg == 0 && fd == d) g_captured[bb * NHC + oc] = v0;
                }
            }
        }
    }
}

// ---------------- finalize ----------------
__global__ void finalize_kernel(const int* __restrict__ N0, float* __restrict__ out)
{
    __shared__ int order[BATCH];
    if (threadIdx.x == 0) {
        int fd[BATCH];
        int cnt[13];
        for (int i = 0; i < 13; i++) cnt[i] = 0;
        for (int bb = 0; bb < BATCH; bb++) {
            fd[bb] = finish_depth(N0[bb]);
            cnt[fd[bb]]++;
        }
        int pos[13];
        int run = 0;
        for (int i = 0; i < 13; i++) { pos[i] = run; run += cnt[i]; }
        for (int bb = 0; bb < BATCH; bb++) order[pos[fd[bb]]++] = bb;
    }
    __syncthreads();
    for (int i = threadIdx.x; i < BATCH * NHC; i += blockDim.x) {
        int row = i >> 8, c = i & 255;
        out[i] = g_captured[order[row] * NHC + c];
    }
}

// ---------------- launch ----------------
extern "C" void kernel_launch(void* const* d_in, const int* in_sizes, int n_in,
                              void* d_out, int out_size)
{
    const float* h  = (const float*)d_in[0];
    const int*   N0 = (const int*)d_in[1];
    const float* w1 = (const float*)d_in[2];
    const float* b1 = (const float*)d_in[3];
    const float* w2 = (const float*)d_in[4];
    const float* b2 = (const float*)d_in[5];

    cudaFuncSetAttribute(conv1_mma, cudaFuncAttributeMaxDynamicSharedMemorySize, SM_DYN);
    cudaFuncSetAttribute(conv2_mma, cudaFuncAttributeMaxDynamicSharedMemorySize, SM_DYN);

    {
        long long tot = (long long)BATCH * NHC * TMAX;
        prep_input<<<(int)((tot + 255) / 256), 256>>>(h);
        prep_w1<<<(4 * FRAG_PER_MT + 255) / 256, 256>>>(w1);
        prep_w2<<<(2 * FRAG_PER_MT + 255) / 256, 256>>>(w2);
        prep_wdep<<<1, 512>>>(w1);
    }

    unsigned* hp0; unsigned* hp1; unsigned* inp;
    cudaGetSymbolAddress((void**)&hp0, g_hplane0);
    cudaGetSymbolAddress((void**)&hp1, g_hplane1);
    cudaGetSymbolAddress((void**)&inp, g_inplane);

    for (int d = 0; d < 12; d++) {
        int T_in  = TMAX >> d;
        int T_out = T_in >> 1;
        int tiles = (T_out + NT - 1) / NT;
        float dval = (float)log1p((double)d);
        const unsigned* plane = (d == 0) ? inp : (((d - 1) & 1) ? hp1 : hp0);
        conv1_mma<<<dim3(tiles, 4, BATCH / 2), 256, SM_DYN>>>(N0, b1, plane, d, T_in, T_out, dval);
        conv2_mma<<<dim3(tiles, 2, BATCH / 2), 256, SM_DYN>>>(N0, b2, d, T_out);
    }
    finalize_kernel<<<1, 256>>>(N0, (float*)d_out);
}

// round 11
// speedup vs baseline: 1.2451x; 1.2451x over previous
#include <cuda_runtime.h>
#include <cuda_bf16.h>
#include <math.h>

#define NHC 256
#define BATCH 64
#define TMAX 4096
#define TOUT_MAX 2048
#define KDIM 1280
#define KC 64
#define NCHUNK 20
#define NT 64
#define APAD 72
#define FRAG_PER_MT (NCHUNK*4*8*32)   // 20480 uint4 per Mtile

// ---------------- device global scratch ----------------
__device__ float g_bufL[BATCH*NHC*TOUT_MAX];
__device__ unsigned g_inplane[BATCH*NHC*TMAX];     // packed (hi<<16)|lo bf16
__device__ unsigned g_hplane0[BATCH*NHC*TOUT_MAX];
__device__ unsigned g_hplane1[BATCH*NHC*TOUT_MAX];
__device__ unsigned g_rplane [BATCH*NHC*TOUT_MAX];
__device__ float g_captured[BATCH*NHC];
__device__ float g_wdep[512*8];                    // wd[0..4], sum, pad
// A fragments in mma register order: [Mt][ch][ks][tile(8)][lane(32)] uint4
__device__ __align__(16) uint4 g_a1hiF[4*FRAG_PER_MT];
__device__ __align__(16) uint4 g_a1loF[4*FRAG_PER_MT];
__device__ __align__(16) uint4 g_a2hiF[2*FRAG_PER_MT];
__device__ __align__(16) uint4 g_a2loF[2*FRAG_PER_MT];

// ---------------- helpers ----------------
__device__ __forceinline__ unsigned smem_u32(const void* p) {
    unsigned a;
    asm("{ .reg .u64 t; cvta.to.shared.u64 t, %1; cvt.u32.u64 %0, t; }" : "=r"(a) : "l"(p));
    return a;
}
__device__ __forceinline__ unsigned pack_hl(float v) {
    __nv_bfloat16 h = __float2bfloat16(v);
    float hf = __bfloat162float(h);
    __nv_bfloat16 l = __float2bfloat16(v - hf);
    unsigned short hb = *reinterpret_cast<unsigned short*>(&h);
    unsigned short lb = *reinterpret_cast<unsigned short*>(&l);
    return ((unsigned)hb << 16) | (unsigned)lb;
}
__device__ __forceinline__ int finish_depth(int n) {
    #pragma unroll 1
    for (int dd = 0; dd < 12; dd++) {
        n = (n - 1) / 2 + 1;
        if (n <= 1) return dd;
    }
    return 11;
}
__device__ __forceinline__ void ldm4t(unsigned* f, unsigned addr) {
    asm volatile("ldmatrix.sync.aligned.m8n8.x4.trans.shared.b16 {%0,%1,%2,%3}, [%4];"
        : "=r"(f[0]), "=r"(f[1]), "=r"(f[2]), "=r"(f[3]) : "r"(addr));
}
__device__ __forceinline__ void mma16816(float* c, const unsigned* a, const unsigned* b) {
    asm volatile("mma.sync.aligned.m16n8k16.row.col.f32.bf16.bf16.f32 "
        "{%0,%1,%2,%3}, {%4,%5,%6,%7}, {%8,%9}, {%0,%1,%2,%3};"
        : "+f"(c[0]), "+f"(c[1]), "+f"(c[2]), "+f"(c[3])
        : "r"(a[0]), "r"(a[1]), "r"(a[2]), "r"(a[3]), "r"(b[0]), "r"(b[1]));
}

#define SM_STAGE 18432       // 9216 hi + 9216 lo per stage
#define SM_DYN   36864

// ---------------- prep kernels ----------------
__global__ void prep_input(const float* __restrict__ h) {
    long long idx = (long long)blockIdx.x * blockDim.x + threadIdx.x;
    if (idx < (long long)BATCH * NHC * TMAX)
        g_inplane[idx] = pack_hl(h[idx]);
}
__global__ void prep_w1(const float* __restrict__ w1) {
    int idx = blockIdx.x * blockDim.x + threadIdx.x;
    if (idx >= 4 * FRAG_PER_MT) return;
    int lane = idx & 31;
    int tile = (idx >> 5) & 7;
    int ks   = (idx >> 8) & 3;
    int rest = idx >> 10;          // Mt*20 + ch
    int ch = rest % NCHUNK;
    int Mt = rest / NCHUNK;
    int r0 = tile * 16 + (lane >> 2);
    int c0 = ks * 16 + (lane & 3) * 2;
    unsigned hi[4], lo[4];
    #pragma unroll
    for (int e = 0; e < 4; e++) {
        int rr = r0 + (e & 1) * 8;
        int cc = c0 + (e >> 1) * 8;
        unsigned h2 = 0, l2 = 0;
        #pragma unroll
        for (int j = 0; j < 2; j++) {
            int kg = ch * KC + cc + j;
            int ic = kg / 5, kk = kg - 5 * ic;
            int oc = Mt * 128 + rr;
            float w = w1[(oc * 257 + ic) * 5 + kk];
            __nv_bfloat16 h = __float2bfloat16(w);
            __nv_bfloat16 l = __float2bfloat16(w - __bfloat162float(h));
            h2 |= ((unsigned)*(unsigned short*)&h) << (16 * j);
            l2 |= ((unsigned)*(unsigned short*)&l) << (16 * j);
        }
        hi[e] = h2; lo[e] = l2;
    }
    g_a1hiF[idx] = make_uint4(hi[0], hi[1], hi[2], hi[3]);
    g_a1loF[idx] = make_uint4(lo[0], lo[1], lo[2], lo[3]);
}
__global__ void prep_w2(const float* __restrict__ w2) {
    int idx = blockIdx.x * blockDim.x + threadIdx.x;
    if (idx >= 2 * FRAG_PER_MT) return;
    int lane = idx & 31;
    int tile = (idx >> 5) & 7;
    int ks   = (idx >> 8) & 3;
    int rest = idx >> 10;
    int ch = rest % NCHUNK;
    int Mt = rest / NCHUNK;
    int r0 = tile * 16 + (lane >> 2);
    int c0 = ks * 16 + (lane & 3) * 2;
    unsigned hi[4], lo[4];
    #pragma unroll
    for (int e = 0; e < 4; e++) {
        int rr = r0 + (e & 1) * 8;
        int cc = c0 + (e >> 1) * 8;
        unsigned h2 = 0, l2 = 0;
        #pragma unroll
        for (int j = 0; j < 2; j++) {
            int kg = ch * KC + cc + j;
            int ic = kg / 5, kk = kg - 5 * ic;
            int oc = Mt * 128 + rr;
            float w = w2[(oc * 256 + ic) * 5 + kk];
            __nv_bfloat16 h = __float2bfloat16(w);
            __nv_bfloat16 l = __float2bfloat16(w - __bfloat162float(h));
            h2 |= ((unsigned)*(unsigned short*)&h) << (16 * j);
            l2 |= ((unsigned)*(unsigned short*)&l) << (16 * j);
        }
        hi[e] = h2; lo[e] = l2;
    }
    g_a2hiF[idx] = make_uint4(hi[0], hi[1], hi[2], hi[3]);
    g_a2loF[idx] = make_uint4(lo[0], lo[1], lo[2], lo[3]);
}
__global__ void prep_wdep(const float* __restrict__ w1) {
    int oc = blockIdx.x * blockDim.x + threadIdx.x;
    if (oc >= 512) return;
    float s = 0.f;
    #pragma unroll
    for (int k = 0; k < 5; k++) {
        float w = w1[(oc * 257 + 256) * 5 + k];
        g_wdep[oc * 8 + k] = w;
        s += w;
    }
    g_wdep[oc * 8 + 5] = s;
    g_wdep[oc * 8 + 6] = 0.f;
    g_wdep[oc * 8 + 7] = 0.f;
}

// ---------------- conv1 (stride 2) ----------------
__global__ __launch_bounds__(256, 2) void conv1_mma(
    const int* __restrict__ N0, const float* __restrict__ b1,
    const unsigned* __restrict__ plane,
    int d, int T_in, int T_out, float dval)
{
    extern __shared__ char smc[];
    const unsigned smb = smem_u32(smc);
    const int tid = threadIdx.x;
    const int b = blockIdx.z, Mtile = blockIdx.y, t0 = blockIdx.x * NT;
    const int lane = tid & 31, q = lane >> 3, r = lane & 7;
    const int w8 = tid >> 5, wmi = w8 >> 1, wni = w8 & 1;

    const int n0v = N0[b];
    const int Ncur = (n0v + (1 << d) - 1) >> d;
    const int Nnew = (n0v + (2 << d) - 1) >> (d + 1);

    const unsigned bOff0 = (unsigned)(((q & 1) * 8 + r) * (APAD * 2) + (wni * 32 + (q >> 1) * 8) * 2);
    const unsigned bOff1 = bOff0 + 32;

    float acc[2][4][4];
    #pragma unroll
    for (int mt = 0; mt < 2; mt++)
        #pragma unroll
        for (int nt = 0; nt < 4; nt++)
            #pragma unroll
            for (int e = 0; e < 4; e++) acc[mt][nt][e] = 0.f;

    const int pbase = 2 * (t0 + 2 * lane) - 2;
    unsigned v[16];

    auto bload = [&](int ch) {
        #pragma unroll
        for (int i = 0; i < 8; i++) {
            int kl = i * 8 + w8;
            int kg = ch * KC + kl;
            int ic = kg / 5, kk = kg - 5 * ic;
            unsigned base = (unsigned)(b * NHC + ic) * (unsigned)T_in;
            int p0 = pbase + kk;
            int p1 = p0 + 2;
            v[2 * i]     = (p0 >= 0 && p0 < Ncur) ? plane[base + p0] : 0u;
            v[2 * i + 1] = (p1 >= 0 && p1 < Ncur) ? plane[base + p1] : 0u;
        }
    };
    auto bstore = [&](int st) {
        unsigned* bh = (unsigned*)(smc + st * SM_STAGE);
        unsigned* bl = bh + 2304;
        #pragma unroll
        for (int i = 0; i < 8; i++) {
            int kl = i * 8 + w8;
            int so = (kl * APAD + 2 * lane) >> 1;
            unsigned v0 = v[2 * i], v1 = v[2 * i + 1];
            bh[so] = (v0 >> 16) | (v1 & 0xFFFF0000u);
            bl[so] = (v0 & 0xFFFFu) | (v1 << 16);
        }
    };

    const uint4* Ah0 = g_a1hiF + (size_t)Mtile * FRAG_PER_MT;
    const uint4* Al0 = g_a1loF + (size_t)Mtile * FRAG_PER_MT;

    bload(0);
    for (int ch = 0; ch < NCHUNK; ch++) {
        const int st = ch & 1;
        bstore(st);
        __syncthreads();
        if (ch + 1 < NCHUNK) bload(ch + 1);
        const unsigned bbase = smb + st * SM_STAGE;
        #pragma unroll
        for (int ks = 0; ks < 4; ks++) {
            const int fidx = ((ch * 4 + ks) * 8 + wmi * 2) * 32 + lane;
            const unsigned kr = (unsigned)(ks * 16 * (APAD * 2));
            unsigned bhf[4][2], blf[4][2], f[4];
            ldm4t(f, bbase + bOff0 + kr);
            bhf[0][0] = f[0]; bhf[0][1] = f[1]; bhf[1][0] = f[2]; bhf[1][1] = f[3];
            ldm4t(f, bbase + bOff1 + kr);
            bhf[2][0] = f[0]; bhf[2][1] = f[1]; bhf[3][0] = f[2]; bhf[3][1] = f[3];
            ldm4t(f, bbase + 9216 + bOff0 + kr);
            blf[0][0] = f[0]; blf[0][1] = f[1]; blf[1][0] = f[2]; blf[1][1] = f[3];
            ldm4t(f, bbase + 9216 + bOff1 + kr);
            blf[2][0] = f[0]; blf[2][1] = f[1]; blf[3][0] = f[2]; blf[3][1] = f[3];
            #pragma unroll
            for (int mt = 0; mt < 2; mt++) {
                uint4 fh = Ah0[fidx + mt * 32];
                uint4 fl = Al0[fidx + mt * 32];
                const unsigned* Ah = (const unsigned*)&fh;
                const unsigned* Al = (const unsigned*)&fl;
                #pragma unroll
                for (int nt = 0; nt < 4; nt++) {
                    mma16816(acc[mt][nt], Ah, bhf[nt]);
                    mma16816(acc[mt][nt], Ah, blf[nt]);
                    mma16816(acc[mt][nt], Al, bhf[nt]);
                }
            }
        }
    }

    // epilogue
    const int crow = lane >> 2, ccol = (lane & 3) * 2;
    const bool dep = (dval != 0.f);
    #pragma unroll
    for (int mt = 0; mt < 2; mt++) {
        #pragma unroll
        for (int rh = 0; rh < 2; rh++) {
            const int oc = Mtile * 128 + wmi * 32 + mt * 16 + rh * 8 + crow;
            const float bias = b1[oc];
            float wd[5], sfull = 0.f;
            if (dep) {
                float4 wA = *(const float4*)&g_wdep[oc * 8];
                float2 wB = *(const float2*)&g_wdep[oc * 8 + 4];
                wd[0] = wA.x; wd[1] = wA.y; wd[2] = wA.z; wd[3] = wA.w; wd[4] = wB.x;
                sfull = wB.y;
            }
            auto dcor = [&](int t) -> float {
                if (t >= 1 && 2 * t + 2 < Ncur) return sfull;
                float s = 0.f;
                #pragma unroll
                for (int k = 0; k < 5; k++) {
                    int p = 2 * t + k - 2;
                    if (p >= 0 && p < Ncur) s += wd[k];
                }
                return s;
            };
            #pragma unroll
            for (int nt = 0; nt < 4; nt++) {
                const int tg = t0 + wni * 32 + nt * 8 + ccol;
                float c0v = acc[mt][nt][rh * 2 + 0] + bias;
                float c1v = acc[mt][nt][rh * 2 + 1] + bias;
                if (dep) {
                    c0v += dval * dcor(tg);
                    c1v += dval * dcor(tg + 1);
                }
                if (Mtile < 2) {
                    size_t off = (size_t)(b * NHC + oc) * T_out + tg;
                    if (tg + 1 < T_out)      *(float2*)&g_bufL[off] = make_float2(c0v, c1v);
                    else if (tg < T_out)     g_bufL[off] = c0v;
                } else {
                    float r0v = fmaxf(c0v, 0.f); if (tg     >= Nnew) r0v = 0.f;
                    float r1v = fmaxf(c1v, 0.f); if (tg + 1 >= Nnew) r1v = 0.f;
                    size_t off = (size_t)(b * NHC + oc - 256) * T_out + tg;
                    if (tg + 1 < T_out)      *(uint2*)&g_rplane[off] = make_uint2(pack_hl(r0v), pack_hl(r1v));
                    else if (tg < T_out)     g_rplane[off] = pack_hl(r0v);
                }
            }
        }
    }
}

// ---------------- conv2 (stride 1) ----------------
__global__ __launch_bounds__(256, 2) void conv2_mma(
    const int* __restrict__ N0, const float* __restrict__ b2,
    int d, int T_out)
{
    extern __shared__ char smc[];
    const unsigned smb = smem_u32(smc);
    const int tid = threadIdx.x;
    const int b = blockIdx.z, Mtile = blockIdx.y, t0 = blockIdx.x * NT;
    const int lane = tid & 31, q = lane >> 3, r = lane & 7;
    const int w8 = tid >> 5, wmi = w8 >> 1, wni = w8 & 1;
    unsigned* hout = (d & 1) ? g_hplane1 : g_hplane0;

    const unsigned bOff0 = (unsigned)(((q & 1) * 8 + r) * (APAD * 2) + (wni * 32 + (q >> 1) * 8) * 2);
    const unsigned bOff1 = bOff0 + 32;

    float acc[2][4][4];
    #pragma unroll
    for (int mt = 0; mt < 2; mt++)
        #pragma unroll
        for (int nt = 0; nt < 4; nt++)
            #pragma unroll
            for (int e = 0; e < 4; e++) acc[mt][nt][e] = 0.f;

    const int pbase = t0 + 2 * lane - 2;
    unsigned v[16];

    auto bload = [&](int ch) {
        #pragma unroll
        for (int i = 0; i < 8; i++) {
            int kl = i * 8 + w8;
            int kg = ch * KC + kl;
            int ic = kg / 5, kk = kg - 5 * ic;
            unsigned base = (unsigned)(b * NHC + ic) * (unsigned)T_out;
            int p0 = pbase + kk;
            int p1 = p0 + 1;
            v[2 * i]     = (p0 >= 0 && p0 < T_out) ? g_rplane[base + p0] : 0u;
            v[2 * i + 1] = (p1 >= 0 && p1 < T_out) ? g_rplane[base + p1] : 0u;
        }
    };
    auto bstore = [&](int st) {
        unsigned* bh = (unsigned*)(smc + st * SM_STAGE);
        unsigned* bl = bh + 2304;
        #pragma unroll
        for (int i = 0; i < 8; i++) {
            int kl = i * 8 + w8;
            int so = (kl * APAD + 2 * lane) >> 1;
            unsigned v0 = v[2 * i], v1 = v[2 * i + 1];
            bh[so] = (v0 >> 16) | (v1 & 0xFFFF0000u);
            bl[so] = (v0 & 0xFFFFu) | (v1 << 16);
        }
    };

    const uint4* Ah0 = g_a2hiF + (size_t)Mtile * FRAG_PER_MT;
    const uint4* Al0 = g_a2loF + (size_t)Mtile * FRAG_PER_MT;

    bload(0);
    for (int ch = 0; ch < NCHUNK; ch++) {
        const int st = ch & 1;
        bstore(st);
        __syncthreads();
        if (ch + 1 < NCHUNK) bload(ch + 1);
        const unsigned bbase = smb + st * SM_STAGE;
        #pragma unroll
        for (int ks = 0; ks < 4; ks++) {
            const int fidx = ((ch * 4 + ks) * 8 + wmi * 2) * 32 + lane;
            const unsigned kr = (unsigned)(ks * 16 * (APAD * 2));
            unsigned bhf[4][2], blf[4][2], f[4];
            ldm4t(f, bbase + bOff0 + kr);
            bhf[0][0] = f[0]; bhf[0][1] = f[1]; bhf[1][0] = f[2]; bhf[1][1] = f[3];
            ldm4t(f, bbase + bOff1 + kr);
            bhf[2][0] = f[0]; bhf[2][1] = f[1]; bhf[3][0] = f[2]; bhf[3][1] = f[3];
            ldm4t(f, bbase + 9216 + bOff0 + kr);
            blf[0][0] = f[0]; blf[0][1] = f[1]; blf[1][0] = f[2]; blf[1][1] = f[3];
            ldm4t(f, bbase + 9216 + bOff1 + kr);
            blf[2][0] = f[0]; blf[2][1] = f[1]; blf[3][0] = f[2]; blf[3][1] = f[3];
            #pragma unroll
            for (int mt = 0; mt < 2; mt++) {
                uint4 fh = Ah0[fidx + mt * 32];
                uint4 fl = Al0[fidx + mt * 32];
                const unsigned* Ah = (const unsigned*)&fh;
                const unsigned* Al = (const unsigned*)&fl;
                #pragma unroll
                for (int nt = 0; nt < 4; nt++) {
                    mma16816(acc[mt][nt], Ah, bhf[nt]);
                    mma16816(acc[mt][nt], Ah, blf[nt]);
                    mma16816(acc[mt][nt], Al, bhf[nt]);
                }
            }
        }
    }

    const int crow = lane >> 2, ccol = (lane & 3) * 2;
    const int fd = finish_depth(N0[b]);
    #pragma unroll
    for (int mt = 0; mt < 2; mt++) {
        #pragma unroll
        for (int rh = 0; rh < 2; rh++) {
            const int oc = Mtile * 128 + wmi * 32 + mt * 16 + rh * 8 + crow;
            const float bias = b2[oc];
            #pragma unroll
            for (int nt = 0; nt < 4; nt++) {
                const int tg = t0 + wni * 32 + nt * 8 + ccol;
                const float c0v = acc[mt][nt][rh * 2 + 0] + bias;
                const float c1v = acc[mt][nt][rh * 2 + 1] + bias;
                size_t off = (size_t)(b * NHC + oc) * T_out + tg;
                if (tg + 1 < T_out) {
                    float2 L = *(const float2*)&g_bufL[off];
                    float v0 = fmaxf(c0v + L.x, 0.f);
                    float v1 = fmaxf(c1v + L.y, 0.f);
                    *(uint2*)&hout[off] = make_uint2(pack_hl(v0), pack_hl(v1));
                    if (tg == 0 && fd == d) g_captured[b * NHC + oc] = v0;
                } else if (tg < T_out) {
                    float v0 = fmaxf(c0v + g_bufL[off], 0.f);
                    hout[off] = pack_hl(v0);
                    if (tg == 0 && fd == d) g_captured[b * NHC + oc] = v0;
                }
            }
        }
    }
}

// ---------------- finalize ----------------
__global__ void finalize_kernel(const int* __restrict__ N0, float* __restrict__ out)
{
    __shared__ int order[BATCH];
    if (threadIdx.x == 0) {
        int fd[BATCH];
        int cnt[13];
        for (int i = 0; i < 13; i++) cnt[i] = 0;
        for (int bb = 0; bb < BATCH; bb++) {
            fd[bb] = finish_depth(N0[bb]);
            cnt[fd[bb]]++;
        }
        int pos[13];
        int run = 0;
        for (int i = 0; i < 13; i++) { pos[i] = run; run += cnt[i]; }
        for (int bb = 0; bb < BATCH; bb++) order[pos[fd[bb]]++] = bb;
    }
    __syncthreads();
    for (int i = threadIdx.x; i < BATCH * NHC; i += blockDim.x) {
        int row = i >> 8, c = i & 255;
        out[i] = g_captured[order[row] * NHC + c];
    }
}

// ---------------- launch ----------------
extern "C" void kernel_launch(void* const* d_in, const int* in_sizes, int n_in,
                              void* d_out, int out_size)
{
    const float* h  = (const float*)d_in[0];
    const int*   N0 = (const int*)d_in[1];
    const float* w1 = (const float*)d_in[2];
    const float* b1 = (const float*)d_in[3];
    const float* w2 = (const float*)d_in[4];
    const float* b2 = (const float*)d_in[5];

    cudaFuncSetAttribute(conv1_mma, cudaFuncAttributeMaxDynamicSharedMemorySize, SM_DYN);
    cudaFuncSetAttribute(conv2_mma, cudaFuncAttributeMaxDynamicSharedMemorySize, SM_DYN);

    {
        long long tot = (long long)BATCH * NHC * TMAX;
        prep_input<<<(int)((tot + 255) / 256), 256>>>(h);
        prep_w1<<<(4 * FRAG_PER_MT + 255) / 256, 256>>>(w1);
        prep_w2<<<(2 * FRAG_PER_MT + 255) / 256, 256>>>(w2);
        prep_wdep<<<2, 256>>>(w1);
    }

    unsigned* hp0; unsigned* hp1; unsigned* inp;
    cudaGetSymbolAddress((void**)&hp0, g_hplane0);
    cudaGetSymbolAddress((void**)&hp1, g_hplane1);
    cudaGetSymbolAddress((void**)&inp, g_inplane);

    for (int d = 0; d < 12; d++) {
        int T_in  = TMAX >> d;
        int T_out = T_in >> 1;
        int tiles = (T_out + NT - 1) / NT;
        float dval = (float)log1p((double)d);
        const unsigned* plane = (d == 0) ? inp : (((d - 1) & 1) ? hp1 : hp0);
        conv1_mma<<<dim3(tiles, 4, BATCH), 256, SM_DYN>>>(N0, b1, plane, d, T_in, T_out, dval);
        conv2_mma<<<dim3(tiles, 2, BATCH), 256, SM_DYN>>>(N0, b2, d, T_out);
    }
    finalize_kernel<<<1, 256>>>(N0, (float*)d_out);
}

// round 13
// speedup vs baseline: 1.9788x; 1.5893x over previous
#include <cuda_runtime.h>
#include <cuda_bf16.h>
#include <math.h>

#define NHC 256
#define BATCH 64
#define TMAX 4096
#define TOUT_MAX 2048
#define KDIM 1280
#define KC 64
#define NCHUNK 20
#define NT 64
#define APAD 72
#define FRAG_PER_MT (NCHUNK*4*8*32)   // 20480 uint4 per Mtile

// ---------------- device global scratch ----------------
__device__ float g_bufL[BATCH*NHC*TOUT_MAX];
__device__ unsigned g_inplane[BATCH*NHC*TMAX];     // packed (hi<<16)|lo bf16
__device__ unsigned g_hplane0[BATCH*NHC*TOUT_MAX];
__device__ unsigned g_hplane1[BATCH*NHC*TOUT_MAX];
__device__ unsigned g_rplane [BATCH*NHC*TOUT_MAX];
__device__ float g_captured[BATCH*NHC];
__device__ float g_wdep[512*8];                    // wd[0..4], sum, pad
// A fragments in mma register order: [Mt][ch][ks][tile(8)][lane(32)] uint4
__device__ __align__(16) uint4 g_a1hiF[4*FRAG_PER_MT];
__device__ __align__(16) uint4 g_a1loF[4*FRAG_PER_MT];
__device__ __align__(16) uint4 g_a2hiF[2*FRAG_PER_MT];
__device__ __align__(16) uint4 g_a2loF[2*FRAG_PER_MT];

// ---------------- helpers ----------------
__device__ __forceinline__ unsigned smem_u32(const void* p) {
    unsigned a;
    asm("{ .reg .u64 t; cvta.to.shared.u64 t, %1; cvt.u32.u64 %0, t; }" : "=r"(a) : "l"(p));
    return a;
}
__device__ __forceinline__ unsigned pack_hl(float v) {
    __nv_bfloat16 h = __float2bfloat16(v);
    float hf = __bfloat162float(h);
    __nv_bfloat16 l = __float2bfloat16(v - hf);
    unsigned short hb = *reinterpret_cast<unsigned short*>(&h);
    unsigned short lb = *reinterpret_cast<unsigned short*>(&l);
    return ((unsigned)hb << 16) | (unsigned)lb;
}
__device__ __forceinline__ int finish_depth(int n) {
    #pragma unroll 1
    for (int dd = 0; dd < 12; dd++) {
        n = (n - 1) / 2 + 1;
        if (n <= 1) return dd;
    }
    return 11;
}
__device__ __forceinline__ void ldm4t(unsigned* f, unsigned addr) {
    asm volatile("ldmatrix.sync.aligned.m8n8.x4.trans.shared.b16 {%0,%1,%2,%3}, [%4];"
        : "=r"(f[0]), "=r"(f[1]), "=r"(f[2]), "=r"(f[3]) : "r"(addr));
}
__device__ __forceinline__ void mma16816(float* c, const unsigned* a, const unsigned* b) {
    asm volatile("mma.sync.aligned.m16n8k16.row.col.f32.bf16.bf16.f32 "
        "{%0,%1,%2,%3}, {%4,%5,%6,%7}, {%8,%9}, {%0,%1,%2,%3};"
        : "+f"(c[0]), "+f"(c[1]), "+f"(c[2]), "+f"(c[3])
        : "r"(a[0]), "r"(a[1]), "r"(a[2]), "r"(a[3]), "r"(b[0]), "r"(b[1]));
}

#define SM_STAGE 18432       // 9216 hi + 9216 lo per stage
#define SM_DYN   36864

// ---------------- prep kernels ----------------
__global__ void prep_input(const float* __restrict__ h) {
    long long idx = (long long)blockIdx.x * blockDim.x + threadIdx.x;
    if (idx < (long long)BATCH * NHC * TMAX)
        g_inplane[idx] = pack_hl(h[idx]);
}
__global__ void prep_w1(const float* __restrict__ w1) {
    int idx = blockIdx.x * blockDim.x + threadIdx.x;
    if (idx >= 4 * FRAG_PER_MT) return;
    int lane = idx & 31;
    int tile = (idx >> 5) & 7;
    int ks   = (idx >> 8) & 3;
    int rest = idx >> 10;          // Mt*20 + ch
    int ch = rest % NCHUNK;
    int Mt = rest / NCHUNK;
    int r0 = tile * 16 + (lane >> 2);
    int c0 = ks * 16 + (lane & 3) * 2;
    unsigned hi[4], lo[4];
    #pragma unroll
    for (int e = 0; e < 4; e++) {
        int rr = r0 + (e & 1) * 8;
        int cc = c0 + (e >> 1) * 8;
        unsigned h2 = 0, l2 = 0;
        #pragma unroll
        for (int j = 0; j < 2; j++) {
            int kg = ch * KC + cc + j;
            int ic = kg / 5, kk = kg - 5 * ic;
            int oc = Mt * 128 + rr;
            float w = w1[(oc * 257 + ic) * 5 + kk];
            __nv_bfloat16 h = __float2bfloat16(w);
            __nv_bfloat16 l = __float2bfloat16(w - __bfloat162float(h));
            h2 |= ((unsigned)*(unsigned short*)&h) << (16 * j);
            l2 |= ((unsigned)*(unsigned short*)&l) << (16 * j);
        }
        hi[e] = h2; lo[e] = l2;
    }
    g_a1hiF[idx] = make_uint4(hi[0], hi[1], hi[2], hi[3]);
    g_a1loF[idx] = make_uint4(lo[0], lo[1], lo[2], lo[3]);
}
__global__ void prep_w2(const float* __restrict__ w2) {
    int idx = blockIdx.x * blockDim.x + threadIdx.x;
    if (idx >= 2 * FRAG_PER_MT) return;
    int lane = idx & 31;
    int tile = (idx >> 5) & 7;
    int ks   = (idx >> 8) & 3;
    int rest = idx >> 10;
    int ch = rest % NCHUNK;
    int Mt = rest / NCHUNK;
    int r0 = tile * 16 + (lane >> 2);
    int c0 = ks * 16 + (lane & 3) * 2;
    unsigned hi[4], lo[4];
    #pragma unroll
    for (int e = 0; e < 4; e++) {
        int rr = r0 + (e & 1) * 8;
        int cc = c0 + (e >> 1) * 8;
        unsigned h2 = 0, l2 = 0;
        #pragma unroll
        for (int j = 0; j < 2; j++) {
            int kg = ch * KC + cc + j;
            int ic = kg / 5, kk = kg - 5 * ic;
            int oc = Mt * 128 + rr;
            float w = w2[(oc * 256 + ic) * 5 + kk];
            __nv_bfloat16 h = __float2bfloat16(w);
            __nv_bfloat16 l = __float2bfloat16(w - __bfloat162float(h));
            h2 |= ((unsigned)*(unsigned short*)&h) << (16 * j);
            l2 |= ((unsigned)*(unsigned short*)&l) << (16 * j);
        }
        hi[e] = h2; lo[e] = l2;
    }
    g_a2hiF[idx] = make_uint4(hi[0], hi[1], hi[2], hi[3]);
    g_a2loF[idx] = make_uint4(lo[0], lo[1], lo[2], lo[3]);
}
__global__ void prep_wdep(const float* __restrict__ w1) {
    int oc = blockIdx.x * blockDim.x + threadIdx.x;
    if (oc >= 512) return;
    float s = 0.f;
    #pragma unroll
    for (int k = 0; k < 5; k++) {
        float w = w1[(oc * 257 + 256) * 5 + k];
        g_wdep[oc * 8 + k] = w;
        s += w;
    }
    g_wdep[oc * 8 + 5] = s;
    g_wdep[oc * 8 + 6] = 0.f;
    g_wdep[oc * 8 + 7] = 0.f;
}

// ---------------- conv1 (stride 2) ----------------
__global__ __launch_bounds__(256, 2) void conv1_mma(
    const int* __restrict__ N0, const float* __restrict__ b1,
    const unsigned* __restrict__ plane,
    int d, int T_in, int T_out, float dval)
{
    extern __shared__ char smc[];
    const unsigned smb = smem_u32(smc);
    const int tid = threadIdx.x;
    const int b = blockIdx.z, Mtile = blockIdx.y, t0 = blockIdx.x * NT;
    const int lane = tid & 31, q = lane >> 3, r = lane & 7;
    const int w8 = tid >> 5, wmi = w8 >> 1, wni = w8 & 1;

    const int n0v = N0[b];
    const int Ncur = (n0v + (1 << d) - 1) >> d;
    const int Nnew = (n0v + (2 << d) - 1) >> (d + 1);

    // dead-position skip: outputs t >= Nnew are never read downstream
    // (next conv1 masks p < Ncur=Nnew; r is zero-masked; capture is t=0 in tile 0)
    if (t0 > 0 && t0 >= Nnew) return;

    const unsigned bOff0 = (unsigned)(((q & 1) * 8 + r) * (APAD * 2) + (wni * 32 + (q >> 1) * 8) * 2);
    const unsigned bOff1 = bOff0 + 32;

    float acc[2][4][4];
    #pragma unroll
    for (int mt = 0; mt < 2; mt++)
        #pragma unroll
        for (int nt = 0; nt < 4; nt++)
            #pragma unroll
            for (int e = 0; e < 4; e++) acc[mt][nt][e] = 0.f;

    const int pbase = 2 * (t0 + 2 * lane) - 2;
    unsigned v[16];

    auto bload = [&](int ch) {
        #pragma unroll
        for (int i = 0; i < 8; i++) {
            int kl = i * 8 + w8;
            int kg = ch * KC + kl;
            int ic = kg / 5, kk = kg - 5 * ic;
            unsigned base = (unsigned)(b * NHC + ic) * (unsigned)T_in;
            int p0 = pbase + kk;
            int p1 = p0 + 2;
            v[2 * i]     = (p0 >= 0 && p0 < Ncur) ? plane[base + p0] : 0u;
            v[2 * i + 1] = (p1 >= 0 && p1 < Ncur) ? plane[base + p1] : 0u;
        }
    };
    auto bstore = [&](int st) {
        unsigned* bh = (unsigned*)(smc + st * SM_STAGE);
        unsigned* bl = bh + 2304;
        #pragma unroll
        for (int i = 0; i < 8; i++) {
            int kl = i * 8 + w8;
            int so = (kl * APAD + 2 * lane) >> 1;
            unsigned v0 = v[2 * i], v1 = v[2 * i + 1];
            bh[so] = (v0 >> 16) | (v1 & 0xFFFF0000u);
            bl[so] = (v0 & 0xFFFFu) | (v1 << 16);
        }
    };

    const uint4* Ah0 = g_a1hiF + (size_t)Mtile * FRAG_PER_MT;
    const uint4* Al0 = g_a1loF + (size_t)Mtile * FRAG_PER_MT;

    bload(0);
    for (int ch = 0; ch < NCHUNK; ch++) {
        const int st = ch & 1;
        bstore(st);
        __syncthreads();
        if (ch + 1 < NCHUNK) bload(ch + 1);
        const unsigned bbase = smb + st * SM_STAGE;
        #pragma unroll
        for (int ks = 0; ks < 4; ks++) {
            const int fidx = ((ch * 4 + ks) * 8 + wmi * 2) * 32 + lane;
            const unsigned kr = (unsigned)(ks * 16 * (APAD * 2));
            unsigned bhf[4][2], blf[4][2], f[4];
            ldm4t(f, bbase + bOff0 + kr);
            bhf[0][0] = f[0]; bhf[0][1] = f[1]; bhf[1][0] = f[2]; bhf[1][1] = f[3];
            ldm4t(f, bbase + bOff1 + kr);
            bhf[2][0] = f[0]; bhf[2][1] = f[1]; bhf[3][0] = f[2]; bhf[3][1] = f[3];
            ldm4t(f, bbase + 9216 + bOff0 + kr);
            blf[0][0] = f[0]; blf[0][1] = f[1]; blf[1][0] = f[2]; blf[1][1] = f[3];
            ldm4t(f, bbase + 9216 + bOff1 + kr);
            blf[2][0] = f[0]; blf[2][1] = f[1]; blf[3][0] = f[2]; blf[3][1] = f[3];
            #pragma unroll
            for (int mt = 0; mt < 2; mt++) {
                uint4 fh = Ah0[fidx + mt * 32];
                uint4 fl = Al0[fidx + mt * 32];
                const unsigned* Ah = (const unsigned*)&fh;
                const unsigned* Al = (const unsigned*)&fl;
                #pragma unroll
                for (int nt = 0; nt < 4; nt++) {
                    mma16816(acc[mt][nt], Ah, bhf[nt]);
                    mma16816(acc[mt][nt], Ah, blf[nt]);
                    mma16816(acc[mt][nt], Al, bhf[nt]);
                }
            }
        }
    }

    // epilogue
    const int crow = lane >> 2, ccol = (lane & 3) * 2;
    const bool dep = (dval != 0.f);
    #pragma unroll
    for (int mt = 0; mt < 2; mt++) {
        #pragma unroll
        for (int rh = 0; rh < 2; rh++) {
            const int oc = Mtile * 128 + wmi * 32 + mt * 16 + rh * 8 + crow;
            const float bias = b1[oc];
            float wd[5], sfull = 0.f;
            if (dep) {
                float4 wA = *(const float4*)&g_wdep[oc * 8];
                float2 wB = *(const float2*)&g_wdep[oc * 8 + 4];
                wd[0] = wA.x; wd[1] = wA.y; wd[2] = wA.z; wd[3] = wA.w; wd[4] = wB.x;
                sfull = wB.y;
            }
            auto dcor = [&](int t) -> float {
                if (t >= 1 && 2 * t + 2 < Ncur) return sfull;
                float s = 0.f;
                #pragma unroll
                for (int k = 0; k < 5; k++) {
                    int p = 2 * t + k - 2;
                    if (p >= 0 && p < Ncur) s += wd[k];
                }
                return s;
            };
            #pragma unroll
            for (int nt = 0; nt < 4; nt++) {
                const int tg = t0 + wni * 32 + nt * 8 + ccol;
                float c0v = acc[mt][nt][rh * 2 + 0] + bias;
                float c1v = acc[mt][nt][rh * 2 + 1] + bias;
                if (dep) {
                    c0v += dval * dcor(tg);
                    c1v += dval * dcor(tg + 1);
                }
                if (Mtile < 2) {
                    size_t off = (size_t)(b * NHC + oc) * T_out + tg;
                    if (tg + 1 < T_out)      *(float2*)&g_bufL[off] = make_float2(c0v, c1v);
                    else if (tg < T_out)     g_bufL[off] = c0v;
                } else {
                    float r0v = fmaxf(c0v, 0.f); if (tg     >= Nnew) r0v = 0.f;
                    float r1v = fmaxf(c1v, 0.f); if (tg + 1 >= Nnew) r1v = 0.f;
                    size_t off = (size_t)(b * NHC + oc - 256) * T_out + tg;
                    if (tg + 1 < T_out)      *(uint2*)&g_rplane[off] = make_uint2(pack_hl(r0v), pack_hl(r1v));
                    else if (tg < T_out)     g_rplane[off] = pack_hl(r0v);
                }
            }
        }
    }
}

// ---------------- conv2 (stride 1) ----------------
__global__ __launch_bounds__(256, 2) void conv2_mma(
    const int* __restrict__ N0, const float* __restrict__ b2,
    int d, int T_out)
{
    extern __shared__ char smc[];
    const unsigned smb = smem_u32(smc);
    const int tid = threadIdx.x;
    const int b = blockIdx.z, Mtile = blockIdx.y, t0 = blockIdx.x * NT;
    const int lane = tid & 31, q = lane >> 3, r = lane & 7;
    const int w8 = tid >> 5, wmi = w8 >> 1, wni = w8 & 1;
    unsigned* hout = (d & 1) ? g_hplane1 : g_hplane0;

    const int n0v = N0[b];
    const int Nnew = (n0v + (2 << d) - 1) >> (d + 1);

    // dead-position skip (see conv1)
    if (t0 > 0 && t0 >= Nnew) return;

    const unsigned bOff0 = (unsigned)(((q & 1) * 8 + r) * (APAD * 2) + (wni * 32 + (q >> 1) * 8) * 2);
    const unsigned bOff1 = bOff0 + 32;

    float acc[2][4][4];
    #pragma unroll
    for (int mt = 0; mt < 2; mt++)
        #pragma unroll
        for (int nt = 0; nt < 4; nt++)
            #pragma unroll
            for (int e = 0; e < 4; e++) acc[mt][nt][e] = 0.f;

    const int pbase = t0 + 2 * lane - 2;
    unsigned v[16];

    auto bload = [&](int ch) {
        #pragma unroll
        for (int i = 0; i < 8; i++) {
            int kl = i * 8 + w8;
            int kg = ch * KC + kl;
            int ic = kg / 5, kk = kg - 5 * ic;
            unsigned base = (unsigned)(b * NHC + ic) * (unsigned)T_out;
            int p0 = pbase + kk;
            int p1 = p0 + 1;
            v[2 * i]     = (p0 >= 0 && p0 < Nnew) ? g_rplane[base + p0] : 0u;
            v[2 * i + 1] = (p1 >= 0 && p1 < Nnew) ? g_rplane[base + p1] : 0u;
        }
    };
    auto bstore = [&](int st) {
        unsigned* bh = (unsigned*)(smc + st * SM_STAGE);
        unsigned* bl = bh + 2304;
        #pragma unroll
        for (int i = 0; i < 8; i++) {
            int kl = i * 8 + w8;
            int so = (kl * APAD + 2 * lane) >> 1;
            unsigned v0 = v[2 * i], v1 = v[2 * i + 1];
            bh[so] = (v0 >> 16) | (v1 & 0xFFFF0000u);
            bl[so] = (v0 & 0xFFFFu) | (v1 << 16);
        }
    };

    const uint4* Ah0 = g_a2hiF + (size_t)Mtile * FRAG_PER_MT;
    const uint4* Al0 = g_a2loF + (size_t)Mtile * FRAG_PER_MT;

    bload(0);
    for (int ch = 0; ch < NCHUNK; ch++) {
        const int st = ch & 1;
        bstore(st);
        __syncthreads();
        if (ch + 1 < NCHUNK) bload(ch + 1);
        const unsigned bbase = smb + st * SM_STAGE;
        #pragma unroll
        for (int ks = 0; ks < 4; ks++) {
            const int fidx = ((ch * 4 + ks) * 8 + wmi * 2) * 32 + lane;
            const unsigned kr = (unsigned)(ks * 16 * (APAD * 2));
            unsigned bhf[4][2], blf[4][2], f[4];
            ldm4t(f, bbase + bOff0 + kr);
            bhf[0][0] = f[0]; bhf[0][1] = f[1]; bhf[1][0] = f[2]; bhf[1][1] = f[3];
            ldm4t(f, bbase + bOff1 + kr);
            bhf[2][0] = f[0]; bhf[2][1] = f[1]; bhf[3][0] = f[2]; bhf[3][1] = f[3];
            ldm4t(f, bbase + 9216 + bOff0 + kr);
            blf[0][0] = f[0]; blf[0][1] = f[1]; blf[1][0] = f[2]; blf[1][1] = f[3];
            ldm4t(f, bbase + 9216 + bOff1 + kr);
            blf[2][0] = f[0]; blf[2][1] = f[1]; blf[3][0] = f[2]; blf[3][1] = f[3];
            #pragma unroll
            for (int mt = 0; mt < 2; mt++) {
                uint4 fh = Ah0[fidx + mt * 32];
                uint4 fl = Al0[fidx + mt * 32];
                const unsigned* Ah = (const unsigned*)&fh;
                const unsigned* Al = (const unsigned*)&fl;
                #pragma unroll
                for (int nt = 0; nt < 4; nt++) {
                    mma16816(acc[mt][nt], Ah, bhf[nt]);
                    mma16816(acc[mt][nt], Ah, blf[nt]);
                    mma16816(acc[mt][nt], Al, bhf[nt]);
                }
            }
        }
    }

    const int crow = lane >> 2, ccol = (lane & 3) * 2;
    const int fd = finish_depth(n0v);
    #pragma unroll
    for (int mt = 0; mt < 2; mt++) {
        #pragma unroll
        for (int rh = 0; rh < 2; rh++) {
            const int oc = Mtile * 128 + wmi * 32 + mt * 16 + rh * 8 + crow;
            const float bias = b2[oc];
            #pragma unroll
            for (int nt = 0; nt < 4; nt++) {
                const int tg = t0 + wni * 32 + nt * 8 + ccol;
                const float c0v = acc[mt][nt][rh * 2 + 0] + bias;
                const float c1v = acc[mt][nt][rh * 2 + 1] + bias;
                size_t off = (size_t)(b * NHC + oc) * T_out + tg;
                if (tg + 1 < T_out) {
                    float2 L = *(const float2*)&g_bufL[off];
                    float v0 = fmaxf(c0v + L.x, 0.f);
                    float v1 = fmaxf(c1v + L.y, 0.f);
                    *(uint2*)&hout[off] = make_uint2(pack_hl(v0), pack_hl(v1));
                    if (tg == 0 && fd == d) g_captured[b * NHC + oc] = v0;
                } else if (tg < T_out) {
                    float v0 = fmaxf(c0v + g_bufL[off], 0.f);
                    hout[off] = pack_hl(v0);
                    if (tg == 0 && fd == d) g_captured[b * NHC + oc] = v0;
                }
            }
        }
    }
}

// ---------------- finalize ----------------
__global__ void finalize_kernel(const int* __restrict__ N0, float* __restrict__ out)
{
    __shared__ int order[BATCH];
    if (threadIdx.x == 0) {
        int fd[BATCH];
        int cnt[13];
        for (int i = 0; i < 13; i++) cnt[i] = 0;
        for (int bb = 0; bb < BATCH; bb++) {
            fd[bb] = finish_depth(N0[bb]);
            cnt[fd[bb]]++;
        }
        int pos[13];
        int run = 0;
        for (int i = 0; i < 13; i++) { pos[i] = run; run += cnt[i]; }
        for (int bb = 0; bb < BATCH; bb++) order[pos[fd[bb]]++] = bb;
    }
    __syncthreads();
    for (int i = threadIdx.x; i < BATCH * NHC; i += blockDim.x) {
        int row = i >> 8, c = i & 255;
        out[i] = g_captured[order[row] * NHC + c];
    }
}

// ---------------- launch ----------------
extern "C" void kernel_launch(void* const* d_in, const int* in_sizes, int n_in,
                              void* d_out, int out_size)
{
    const float* h  = (const float*)d_in[0];
    const int*   N0 = (const int*)d_in[1];
    const float* w1 = (const float*)d_in[2];
    const float* b1 = (const float*)d_in[3];
    const float* w2 = (const float*)d_in[4];
    const float* b2 = (const float*)d_in[5];

    cudaFuncSetAttribute(conv1_mma, cudaFuncAttributeMaxDynamicSharedMemorySize, SM_DYN);
    cudaFuncSetAttribute(conv2_mma, cudaFuncAttributeMaxDynamicSharedMemorySize, SM_DYN);

    {
        long long tot = (long long)BATCH * NHC * TMAX;
        prep_input<<<(int)((tot + 255) / 256), 256>>>(h);
        prep_w1<<<(4 * FRAG_PER_MT + 255) / 256, 256>>>(w1);
        prep_w2<<<(2 * FRAG_PER_MT + 255) / 256, 256>>>(w2);
        prep_wdep<<<2, 256>>>(w1);
    }

    unsigned* hp0; unsigned* hp1; unsigned* inp;
    cudaGetSymbolAddress((void**)&hp0, g_hplane0);
    cudaGetSymbolAddress((void**)&hp1, g_hplane1);
    cudaGetSymbolAddress((void**)&inp, g_inplane);

    for (int d = 0; d < 12; d++) {
        int T_in  = TMAX >> d;
        int T_out = T_in >> 1;
        int tiles = (T_out + NT - 1) / NT;
        float dval = (float)log1p((double)d);
        const unsigned* plane = (d == 0) ? inp : (((d - 1) & 1) ? hp1 : hp0);
        conv1_mma<<<dim3(tiles, 4, BATCH), 256, SM_DYN>>>(N0, b1, plane, d, T_in, T_out, dval);
        conv2_mma<<<dim3(tiles, 2, BATCH), 256, SM_DYN>>>(N0, b2, d, T_out);
    }
    finalize_kernel<<<1, 256>>>(N0, (float*)d_out);
}

// round 14
// speedup vs baseline: 2.0808x; 1.0515x over previous
#include <cuda_runtime.h>
#include <cuda_bf16.h>
#include <math.h>

#define NHC 256
#define BATCH 64
#define TMAX 4096
#define TOUT_MAX 2048
#define KDIM 1280
#define KC 64
#define NCHUNK 20
#define NT 64
#define APAD 72
#define FRAG_PER_MT (NCHUNK*4*8*32)   // 20480 uint4 per Mtile

// ---------------- device global scratch ----------------
__device__ float g_bufL[BATCH*NHC*TOUT_MAX];
__device__ unsigned g_inplane[BATCH*NHC*TMAX];     // packed (hi<<16)|lo bf16
__device__ unsigned g_hplane0[BATCH*NHC*TOUT_MAX];
__device__ unsigned g_hplane1[BATCH*NHC*TOUT_MAX];
__device__ unsigned g_rplane [BATCH*NHC*TOUT_MAX];
__device__ float g_captured[BATCH*NHC];
__device__ float g_wdep[512*8];                    // wd[0..4], sum, pad
// A fragments in mma register order: [Mt][ch][ks][tile(8)][lane(32)] uint4
__device__ __align__(16) uint4 g_a1hiF[4*FRAG_PER_MT];
__device__ __align__(16) uint4 g_a1loF[4*FRAG_PER_MT];
__device__ __align__(16) uint4 g_a2hiF[2*FRAG_PER_MT];
__device__ __align__(16) uint4 g_a2loF[2*FRAG_PER_MT];

// ---------------- helpers ----------------
__device__ __forceinline__ unsigned smem_u32(const void* p) {
    unsigned a;
    asm("{ .reg .u64 t; cvta.to.shared.u64 t, %1; cvt.u32.u64 %0, t; }" : "=r"(a) : "l"(p));
    return a;
}
__device__ __forceinline__ unsigned pack_hl(float v) {
    __nv_bfloat16 h = __float2bfloat16(v);
    float hf = __bfloat162float(h);
    __nv_bfloat16 l = __float2bfloat16(v - hf);
    unsigned short hb = *reinterpret_cast<unsigned short*>(&h);
    unsigned short lb = *reinterpret_cast<unsigned short*>(&l);
    return ((unsigned)hb << 16) | (unsigned)lb;
}
__device__ __forceinline__ int finish_depth(int n) {
    #pragma unroll 1
    for (int dd = 0; dd < 12; dd++) {
        n = (n - 1) / 2 + 1;
        if (n <= 1) return dd;
    }
    return 11;
}
__device__ __forceinline__ void ldm4t(unsigned* f, unsigned addr) {
    asm volatile("ldmatrix.sync.aligned.m8n8.x4.trans.shared.b16 {%0,%1,%2,%3}, [%4];"
        : "=r"(f[0]), "=r"(f[1]), "=r"(f[2]), "=r"(f[3]) : "r"(addr));
}
__device__ __forceinline__ void mma16816(float* c, const unsigned* a, const unsigned* b) {
    asm volatile("mma.sync.aligned.m16n8k16.row.col.f32.bf16.bf16.f32 "
        "{%0,%1,%2,%3}, {%4,%5,%6,%7}, {%8,%9}, {%0,%1,%2,%3};"
        : "+f"(c[0]), "+f"(c[1]), "+f"(c[2]), "+f"(c[3])
        : "r"(a[0]), "r"(a[1]), "r"(a[2]), "r"(a[3]), "r"(b[0]), "r"(b[1]));
}

#define SM_STAGE 18432       // 9216 hi + 9216 lo per stage
#define SM_DYN   36864

// ---------------- prep kernels ----------------
__global__ void prep_input(const float* __restrict__ h) {
    long long idx = (long long)blockIdx.x * blockDim.x + threadIdx.x;
    if (idx < (long long)BATCH * NHC * TMAX)
        g_inplane[idx] = pack_hl(h[idx]);
}
__global__ void prep_w1(const float* __restrict__ w1) {
    int idx = blockIdx.x * blockDim.x + threadIdx.x;
    if (idx >= 4 * FRAG_PER_MT) return;
    int lane = idx & 31;
    int tile = (idx >> 5) & 7;
    int ks   = (idx >> 8) & 3;
    int rest = idx >> 10;          // Mt*20 + ch
    int ch = rest % NCHUNK;
    int Mt = rest / NCHUNK;
    int r0 = tile * 16 + (lane >> 2);
    int c0 = ks * 16 + (lane & 3) * 2;
    unsigned hi[4], lo[4];
    #pragma unroll
    for (int e = 0; e < 4; e++) {
        int rr = r0 + (e & 1) * 8;
        int cc = c0 + (e >> 1) * 8;
        unsigned h2 = 0, l2 = 0;
        #pragma unroll
        for (int j = 0; j < 2; j++) {
            int kg = ch * KC + cc + j;
            int ic = kg / 5, kk = kg - 5 * ic;
            int oc = Mt * 128 + rr;
            float w = w1[(oc * 257 + ic) * 5 + kk];
            __nv_bfloat16 h = __float2bfloat16(w);
            __nv_bfloat16 l = __float2bfloat16(w - __bfloat162float(h));
            h2 |= ((unsigned)*(unsigned short*)&h) << (16 * j);
            l2 |= ((unsigned)*(unsigned short*)&l) << (16 * j);
        }
        hi[e] = h2; lo[e] = l2;
    }
    g_a1hiF[idx] = make_uint4(hi[0], hi[1], hi[2], hi[3]);
    g_a1loF[idx] = make_uint4(lo[0], lo[1], lo[2], lo[3]);
}
__global__ void prep_w2(const float* __restrict__ w2) {
    int idx = blockIdx.x * blockDim.x + threadIdx.x;
    if (idx >= 2 * FRAG_PER_MT) return;
    int lane = idx & 31;
    int tile = (idx >> 5) & 7;
    int ks   = (idx >> 8) & 3;
    int rest = idx >> 10;
    int ch = rest % NCHUNK;
    int Mt = rest / NCHUNK;
    int r0 = tile * 16 + (lane >> 2);
    int c0 = ks * 16 + (lane & 3) * 2;
    unsigned hi[4], lo[4];
    #pragma unroll
    for (int e = 0; e < 4; e++) {
        int rr = r0 + (e & 1) * 8;
        int cc = c0 + (e >> 1) * 8;
        unsigned h2 = 0, l2 = 0;
        #pragma unroll
        for (int j = 0; j < 2; j++) {
            int kg = ch * KC + cc + j;
            int ic = kg / 5, kk = kg - 5 * ic;
            int oc = Mt * 128 + rr;
            float w = w2[(oc * 256 + ic) * 5 + kk];
            __nv_bfloat16 h = __float2bfloat16(w);
            __nv_bfloat16 l = __float2bfloat16(w - __bfloat162float(h));
            h2 |= ((unsigned)*(unsigned short*)&h) << (16 * j);
            l2 |= ((unsigned)*(unsigned short*)&l) << (16 * j);
        }
        hi[e] = h2; lo[e] = l2;
    }
    g_a2hiF[idx] = make_uint4(hi[0], hi[1], hi[2], hi[3]);
    g_a2loF[idx] = make_uint4(lo[0], lo[1], lo[2], lo[3]);
}
__global__ void prep_wdep(const float* __restrict__ w1) {
    int oc = blockIdx.x * blockDim.x + threadIdx.x;
    if (oc >= 512) return;
    float s = 0.f;
    #pragma unroll
    for (int k = 0; k < 5; k++) {
        float w = w1[(oc * 257 + 256) * 5 + k];
        g_wdep[oc * 8 + k] = w;
        s += w;
    }
    g_wdep[oc * 8 + 5] = s;
    g_wdep[oc * 8 + 6] = 0.f;
    g_wdep[oc * 8 + 7] = 0.f;
}

// ---------------- conv1 (stride 2) ----------------
__global__ __launch_bounds__(256, 2) void conv1_mma(
    const int* __restrict__ N0, const float* __restrict__ b1,
    const unsigned* __restrict__ plane,
    int d, int T_in, int T_out, float dval)
{
    extern __shared__ char smc[];
    const unsigned smb = smem_u32(smc);
    const int tid = threadIdx.x;
    const int b = blockIdx.z, Mtile = blockIdx.y, t0 = blockIdx.x * NT;
    const int lane = tid & 31, q = lane >> 3, r = lane & 7;
    const int w8 = tid >> 5, wmi = w8 >> 1, wni = w8 & 1;

    const int n0v = N0[b];
    const int Ncur = (n0v + (1 << d) - 1) >> d;
    const int Nnew = (n0v + (2 << d) - 1) >> (d + 1);

    // dead-position skip: outputs t >= Nnew are never read downstream
    if (t0 > 0 && t0 >= Nnew) return;

    const unsigned bOff0 = (unsigned)(((q & 1) * 8 + r) * (APAD * 2) + (wni * 32 + (q >> 1) * 8) * 2);
    const unsigned bOff1 = bOff0 + 32;

    float acc[2][4][4];
    #pragma unroll
    for (int mt = 0; mt < 2; mt++)
        #pragma unroll
        for (int nt = 0; nt < 4; nt++)
            #pragma unroll
            for (int e = 0; e < 4; e++) acc[mt][nt][e] = 0.f;

    const int pbase = 2 * (t0 + 2 * lane) - 2;
    unsigned v[16];

    auto bload = [&](int ch) {
        #pragma unroll
        for (int i = 0; i < 8; i++) {
            int kl = i * 8 + w8;
            int kg = ch * KC + kl;
            int ic = kg / 5, kk = kg - 5 * ic;
            unsigned base = (unsigned)(b * NHC + ic) * (unsigned)T_in;
            int p0 = pbase + kk;
            int p1 = p0 + 2;
            v[2 * i]     = (p0 >= 0 && p0 < Ncur) ? plane[base + p0] : 0u;
            v[2 * i + 1] = (p1 >= 0 && p1 < Ncur) ? plane[base + p1] : 0u;
        }
    };
    auto bstore = [&](int st) {
        unsigned* bh = (unsigned*)(smc + st * SM_STAGE);
        unsigned* bl = bh + 2304;
        #pragma unroll
        for (int i = 0; i < 8; i++) {
            int kl = i * 8 + w8;
            int so = (kl * APAD + 2 * lane) >> 1;
            unsigned v0 = v[2 * i], v1 = v[2 * i + 1];
            bh[so] = (v0 >> 16) | (v1 & 0xFFFF0000u);
            bl[so] = (v0 & 0xFFFFu) | (v1 << 16);
        }
    };

    const uint4* Ah0 = g_a1hiF + (size_t)Mtile * FRAG_PER_MT;
    const uint4* Al0 = g_a1loF + (size_t)Mtile * FRAG_PER_MT;
    const int lbase = wmi * 2 * 32 + lane;

    // A-fragment register pipeline: current step's 4 fragments
    uint4 aH0, aH1, aL0, aL1;
    {
        const int f0 = 0 * 8 * 32 + lbase;
        aH0 = Ah0[f0]; aH1 = Ah0[f0 + 32];
        aL0 = Al0[f0]; aL1 = Al0[f0 + 32];
    }

    bload(0);
    for (int ch = 0; ch < NCHUNK; ch++) {
        const int st = ch & 1;
        bstore(st);
        __syncthreads();
        if (ch + 1 < NCHUNK) bload(ch + 1);
        const unsigned bbase = smb + st * SM_STAGE;
        #pragma unroll
        for (int ks = 0; ks < 4; ks++) {
            // prefetch A fragments for next step (clamped at the last step)
            const int un = ch * 4 + ks + 1;
            const int fn = (un < 80 ? un : 79) * 8 * 32 + lbase;
            uint4 nH0 = Ah0[fn], nH1 = Ah0[fn + 32];
            uint4 nL0 = Al0[fn], nL1 = Al0[fn + 32];

            const unsigned kr = (unsigned)(ks * 16 * (APAD * 2));
            unsigned bhf[4][2], blf[4][2], f[4];
            ldm4t(f, bbase + bOff0 + kr);
            bhf[0][0] = f[0]; bhf[0][1] = f[1]; bhf[1][0] = f[2]; bhf[1][1] = f[3];
            ldm4t(f, bbase + bOff1 + kr);
            bhf[2][0] = f[0]; bhf[2][1] = f[1]; bhf[3][0] = f[2]; bhf[3][1] = f[3];
            ldm4t(f, bbase + 9216 + bOff0 + kr);
            blf[0][0] = f[0]; blf[0][1] = f[1]; blf[1][0] = f[2]; blf[1][1] = f[3];
            ldm4t(f, bbase + 9216 + bOff1 + kr);
            blf[2][0] = f[0]; blf[2][1] = f[1]; blf[3][0] = f[2]; blf[3][1] = f[3];

            const unsigned* Ahc[2] = {(const unsigned*)&aH0, (const unsigned*)&aH1};
            const unsigned* Alc[2] = {(const unsigned*)&aL0, (const unsigned*)&aL1};
            #pragma unroll
            for (int mt = 0; mt < 2; mt++) {
                #pragma unroll
                for (int nt = 0; nt < 4; nt++) {
                    mma16816(acc[mt][nt], Ahc[mt], bhf[nt]);
                    mma16816(acc[mt][nt], Ahc[mt], blf[nt]);
                    mma16816(acc[mt][nt], Alc[mt], bhf[nt]);
                }
            }
            aH0 = nH0; aH1 = nH1; aL0 = nL0; aL1 = nL1;
        }
    }

    // epilogue
    const int crow = lane >> 2, ccol = (lane & 3) * 2;
    const bool dep = (dval != 0.f);
    #pragma unroll
    for (int mt = 0; mt < 2; mt++) {
        #pragma unroll
        for (int rh = 0; rh < 2; rh++) {
            const int oc = Mtile * 128 + wmi * 32 + mt * 16 + rh * 8 + crow;
            const float bias = b1[oc];
            float wd[5], sfull = 0.f;
            if (dep) {
                float4 wA = *(const float4*)&g_wdep[oc * 8];
                float2 wB = *(const float2*)&g_wdep[oc * 8 + 4];
                wd[0] = wA.x; wd[1] = wA.y; wd[2] = wA.z; wd[3] = wA.w; wd[4] = wB.x;
                sfull = wB.y;
            }
            auto dcor = [&](int t) -> float {
                if (t >= 1 && 2 * t + 2 < Ncur) return sfull;
                float s = 0.f;
                #pragma unroll
                for (int k = 0; k < 5; k++) {
                    int p = 2 * t + k - 2;
                    if (p >= 0 && p < Ncur) s += wd[k];
                }
                return s;
            };
            #pragma unroll
            for (int nt = 0; nt < 4; nt++) {
                const int tg = t0 + wni * 32 + nt * 8 + ccol;
                float c0v = acc[mt][nt][rh * 2 + 0] + bias;
                float c1v = acc[mt][nt][rh * 2 + 1] + bias;
                if (dep) {
                    c0v += dval * dcor(tg);
                    c1v += dval * dcor(tg + 1);
                }
                if (Mtile < 2) {
                    size_t off = (size_t)(b * NHC + oc) * T_out + tg;
                    if (tg + 1 < T_out)      *(float2*)&g_bufL[off] = make_float2(c0v, c1v);
                    else if (tg < T_out)     g_bufL[off] = c0v;
                } else {
                    float r0v = fmaxf(c0v, 0.f); if (tg     >= Nnew) r0v = 0.f;
                    float r1v = fmaxf(c1v, 0.f); if (tg + 1 >= Nnew) r1v = 0.f;
                    size_t off = (size_t)(b * NHC + oc - 256) * T_out + tg;
                    if (tg + 1 < T_out)      *(uint2*)&g_rplane[off] = make_uint2(pack_hl(r0v), pack_hl(r1v));
                    else if (tg < T_out)     g_rplane[off] = pack_hl(r0v);
                }
            }
        }
    }
}

// ---------------- conv2 (stride 1) ----------------
__global__ __launch_bounds__(256, 2) void conv2_mma(
    const int* __restrict__ N0, const float* __restrict__ b2,
    int d, int T_out)
{
    extern __shared__ char smc[];
    const unsigned smb = smem_u32(smc);
    const int tid = threadIdx.x;
    const int b = blockIdx.z, Mtile = blockIdx.y, t0 = blockIdx.x * NT;
    const int lane = tid & 31, q = lane >> 3, r = lane & 7;
    const int w8 = tid >> 5, wmi = w8 >> 1, wni = w8 & 1;
    unsigned* hout = (d & 1) ? g_hplane1 : g_hplane0;

    const int n0v = N0[b];
    const int Nnew = (n0v + (2 << d) - 1) >> (d + 1);

    // dead-position skip (see conv1)
    if (t0 > 0 && t0 >= Nnew) return;

    const unsigned bOff0 = (unsigned)(((q & 1) * 8 + r) * (APAD * 2) + (wni * 32 + (q >> 1) * 8) * 2);
    const unsigned bOff1 = bOff0 + 32;

    float acc[2][4][4];
    #pragma unroll
    for (int mt = 0; mt < 2; mt++)
        #pragma unroll
        for (int nt = 0; nt < 4; nt++)
            #pragma unroll
            for (int e = 0; e < 4; e++) acc[mt][nt][e] = 0.f;

    const int pbase = t0 + 2 * lane - 2;
    unsigned v[16];

    auto bload = [&](int ch) {
        #pragma unroll
        for (int i = 0; i < 8; i++) {
            int kl = i * 8 + w8;
            int kg = ch * KC + kl;
            int ic = kg / 5, kk = kg - 5 * ic;
            unsigned base = (unsigned)(b * NHC + ic) * (unsigned)T_out;
            int p0 = pbase + kk;
            int p1 = p0 + 1;
            v[2 * i]     = (p0 >= 0 && p0 < Nnew) ? g_rplane[base + p0] : 0u;
            v[2 * i + 1] = (p1 >= 0 && p1 < Nnew) ? g_rplane[base + p1] : 0u;
        }
    };
    auto bstore = [&](int st) {
        unsigned* bh = (unsigned*)(smc + st * SM_STAGE);
        unsigned* bl = bh + 2304;
        #pragma unroll
        for (int i = 0; i < 8; i++) {
            int kl = i * 8 + w8;
            int so = (kl * APAD + 2 * lane) >> 1;
            unsigned v0 = v[2 * i], v1 = v[2 * i + 1];
            bh[so] = (v0 >> 16) | (v1 & 0xFFFF0000u);
            bl[so] = (v0 & 0xFFFFu) | (v1 << 16);
        }
    };

    const uint4* Ah0 = g_a2hiF + (size_t)Mtile * FRAG_PER_MT;
    const uint4* Al0 = g_a2loF + (size_t)Mtile * FRAG_PER_MT;
    const int lbase = wmi * 2 * 32 + lane;

    uint4 aH0, aH1, aL0, aL1;
    {
        const int f0 = 0 * 8 * 32 + lbase;
        aH0 = Ah0[f0]; aH1 = Ah0[f0 + 32];
        aL0 = Al0[f0]; aL1 = Al0[f0 + 32];
    }

    bload(0);
    for (int ch = 0; ch < NCHUNK; ch++) {
        const int st = ch & 1;
        bstore(st);
        __syncthreads();
        if (ch + 1 < NCHUNK) bload(ch + 1);
        const unsigned bbase = smb + st * SM_STAGE;
        #pragma unroll
        for (int ks = 0; ks < 4; ks++) {
            const int un = ch * 4 + ks + 1;
            const int fn = (un < 80 ? un : 79) * 8 * 32 + lbase;
            uint4 nH0 = Ah0[fn], nH1 = Ah0[fn + 32];
            uint4 nL0 = Al0[fn], nL1 = Al0[fn + 32];

            const unsigned kr = (unsigned)(ks * 16 * (APAD * 2));
            unsigned bhf[4][2], blf[4][2], f[4];
            ldm4t(f, bbase + bOff0 + kr);
            bhf[0][0] = f[0]; bhf[0][1] = f[1]; bhf[1][0] = f[2]; bhf[1][1] = f[3];
            ldm4t(f, bbase + bOff1 + kr);
            bhf[2][0] = f[0]; bhf[2][1] = f[1]; bhf[3][0] = f[2]; bhf[3][1] = f[3];
            ldm4t(f, bbase + 9216 + bOff0 + kr);
            blf[0][0] = f[0]; blf[0][1] = f[1]; blf[1][0] = f[2]; blf[1][1] = f[3];
            ldm4t(f, bbase + 9216 + bOff1 + kr);
            blf[2][0] = f[0]; blf[2][1] = f[1]; blf[3][0] = f[2]; blf[3][1] = f[3];

            const unsigned* Ahc[2] = {(const unsigned*)&aH0, (const unsigned*)&aH1};
            const unsigned* Alc[2] = {(const unsigned*)&aL0, (const unsigned*)&aL1};
            #pragma unroll
            for (int mt = 0; mt < 2; mt++) {
                #pragma unroll
                for (int nt = 0; nt < 4; nt++) {
                    mma16816(acc[mt][nt], Ahc[mt], bhf[nt]);
                    mma16816(acc[mt][nt], Ahc[mt], blf[nt]);
                    mma16816(acc[mt][nt], Alc[mt], bhf[nt]);
                }
            }
            aH0 = nH0; aH1 = nH1; aL0 = nL0; aL1 = nL1;
        }
    }

    const int crow = lane >> 2, ccol = (lane & 3) * 2;
    const int fd = finish_depth(n0v);
    #pragma unroll
    for (int mt = 0; mt < 2; mt++) {
        #pragma unroll
        for (int rh = 0; rh < 2; rh++) {
            const int oc = Mtile * 128 + wmi * 32 + mt * 16 + rh * 8 + crow;
            const float bias = b2[oc];
            #pragma unroll
            for (int nt = 0; nt < 4; nt++) {
                const int tg = t0 + wni * 32 + nt * 8 + ccol;
                const float c0v = acc[mt][nt][rh * 2 + 0] + bias;
                const float c1v = acc[mt][nt][rh * 2 + 1] + bias;
                size_t off = (size_t)(b * NHC + oc) * T_out + tg;
                if (tg + 1 < T_out) {
                    float2 L = *(const float2*)&g_bufL[off];
                    float v0 = fmaxf(c0v + L.x, 0.f);
                    float v1 = fmaxf(c1v + L.y, 0.f);
                    *(uint2*)&hout[off] = make_uint2(pack_hl(v0), pack_hl(v1));
                    if (tg == 0 && fd == d) g_captured[b * NHC + oc] = v0;
                } else if (tg < T_out) {
                    float v0 = fmaxf(c0v + g_bufL[off], 0.f);
                    hout[off] = pack_hl(v0);
                    if (tg == 0 && fd == d) g_captured[b * NHC + oc] = v0;
                }
            }
        }
    }
}

// ---------------- finalize ----------------
__global__ void finalize_kernel(const int* __restrict__ N0, float* __restrict__ out)
{
    __shared__ int order[BATCH];
    if (threadIdx.x == 0) {
        int fd[BATCH];
        int cnt[13];
        for (int i = 0; i < 13; i++) cnt[i] = 0;
        for (int bb = 0; bb < BATCH; bb++) {
            fd[bb] = finish_depth(N0[bb]);
            cnt[fd[bb]]++;
        }
        int pos[13];
        int run = 0;
        for (int i = 0; i < 13; i++) { pos[i] = run; run += cnt[i]; }
        for (int bb = 0; bb < BATCH; bb++) order[pos[fd[bb]]++] = bb;
    }
    __syncthreads();
    for (int i = threadIdx.x; i < BATCH * NHC; i += blockDim.x) {
        int row = i >> 8, c = i & 255;
        out[i] = g_captured[order[row] * NHC + c];
    }
}

// ---------------- launch ----------------
extern "C" void kernel_launch(void* const* d_in, const int* in_sizes, int n_in,
                              void* d_out, int out_size)
{
    const float* h  = (const float*)d_in[0];
    const int*   N0 = (const int*)d_in[1];
    const float* w1 = (const float*)d_in[2];
    const float* b1 = (const float*)d_in[3];
    const float* w2 = (const float*)d_in[4];
    const float* b2 = (const float*)d_in[5];

    cudaFuncSetAttribute(conv1_mma, cudaFuncAttributeMaxDynamicSharedMemorySize, SM_DYN);
    cudaFuncSetAttribute(conv2_mma, cudaFuncAttributeMaxDynamicSharedMemorySize, SM_DYN);

    {
        long long tot = (long long)BATCH * NHC * TMAX;
        prep_input<<<(int)((tot + 255) / 256), 256>>>(h);
        prep_w1<<<(4 * FRAG_PER_MT + 255) / 256, 256>>>(w1);
        prep_w2<<<(2 * FRAG_PER_MT + 255) / 256, 256>>>(w2);
        prep_wdep<<<2, 256>>>(w1);
    }

    unsigned* hp0; unsigned* hp1; unsigned* inp;
    cudaGetSymbolAddress((void**)&hp0, g_hplane0);
    cudaGetSymbolAddress((void**)&hp1, g_hplane1);
    cudaGetSymbolAddress((void**)&inp, g_inplane);

    for (int d = 0; d < 12; d++) {
        int T_in  = TMAX >> d;
        int T_out = T_in >> 1;
        int tiles = (T_out + NT - 1) / NT;
        float dval = (float)log1p((double)d);
        const unsigned* plane = (d == 0) ? inp : (((d - 1) & 1) ? hp1 : hp0);
        conv1_mma<<<dim3(tiles, 4, BATCH), 256, SM_DYN>>>(N0, b1, plane, d, T_in, T_out, dval);
        conv2_mma<<<dim3(tiles, 2, BATCH), 256, SM_DYN>>>(N0, b2, d, T_out);
    }
    finalize_kernel<<<1, 256>>>(N0, (float*)d_out);
}

// round 17
// speedup vs baseline: 2.6460x; 1.2717x over previous
#include <cuda_runtime.h>
#include <cuda_fp16.h>
#include <math.h>

#define NHC 256
#define BATCH 64
#define TMAX 4096
#define TOUT_MAX 2048
#define KDIM 1280
#define KC 64
#define NCHUNK 20
#define NT 64
#define APAD 72
#define FRAG_PER_MT (NCHUNK*4*8*32)   // 20480 uint4 per Mtile

// ---------------- device global scratch ----------------
__device__ float g_bufL[BATCH*NHC*TOUT_MAX];
__device__ unsigned short g_inplane[BATCH*NHC*TMAX];   // fp16 activations
__device__ unsigned short g_hplane0[BATCH*NHC*TOUT_MAX];
__device__ unsigned short g_hplane1[BATCH*NHC*TOUT_MAX];
__device__ unsigned short g_rplane [BATCH*NHC*TOUT_MAX];
__device__ float g_captured[BATCH*NHC];
__device__ float g_wdep[512*8];                    // wd[0..4], sum, pad
// A fragments (fp16 hi / fp16 lo) in mma register order: [Mt][ch][ks][tile(8)][lane(32)] uint4
__device__ __align__(16) uint4 g_a1hiF[4*FRAG_PER_MT];
__device__ __align__(16) uint4 g_a1loF[4*FRAG_PER_MT];
__device__ __align__(16) uint4 g_a2hiF[2*FRAG_PER_MT];
__device__ __align__(16) uint4 g_a2loF[2*FRAG_PER_MT];

// ---------------- helpers ----------------
__device__ __forceinline__ unsigned smem_u32(const void* p) {
    unsigned a;
    asm("{ .reg .u64 t; cvta.to.shared.u64 t, %1; cvt.u32.u64 %0, t; }" : "=r"(a) : "l"(p));
    return a;
}
__device__ __forceinline__ unsigned short f2h(float v) {
    return __half_as_ushort(__float2half_rn(v));
}
__device__ __forceinline__ int finish_depth(int n) {
    #pragma unroll 1
    for (int dd = 0; dd < 12; dd++) {
        n = (n - 1) / 2 + 1;
        if (n <= 1) return dd;
    }
    return 11;
}
__device__ __forceinline__ void ldm4t(unsigned* f, unsigned addr) {
    asm volatile("ldmatrix.sync.aligned.m8n8.x4.trans.shared.b16 {%0,%1,%2,%3}, [%4];"
        : "=r"(f[0]), "=r"(f[1]), "=r"(f[2]), "=r"(f[3]) : "r"(addr));
}
__device__ __forceinline__ void mma16816(float* c, const unsigned* a, const unsigned* b) {
    asm volatile("mma.sync.aligned.m16n8k16.row.col.f32.f16.f16.f32 "
        "{%0,%1,%2,%3}, {%4,%5,%6,%7}, {%8,%9}, {%0,%1,%2,%3};"
        : "+f"(c[0]), "+f"(c[1]), "+f"(c[2]), "+f"(c[3])
        : "r"(a[0]), "r"(a[1]), "r"(a[2]), "r"(a[3]), "r"(b[0]), "r"(b[1]));
}

#define SM_STAGE 9216        // single fp16 B plane per stage: 64 rows * 144 B
#define SM_DYN   18432

// ---------------- prep kernels ----------------
__global__ void prep_input(const float* __restrict__ h) {
    long long idx = (long long)blockIdx.x * blockDim.x + threadIdx.x;
    if (idx < (long long)BATCH * NHC * TMAX)
        g_inplane[idx] = f2h(h[idx]);
}
__global__ void prep_w1(const float* __restrict__ w1) {
    int idx = blockIdx.x * blockDim.x + threadIdx.x;
    if (idx >= 4 * FRAG_PER_MT) return;
    int lane = idx & 31;
    int tile = (idx >> 5) & 7;
    int ks   = (idx >> 8) & 3;
    int rest = idx >> 10;          // Mt*20 + ch
    int ch = rest % NCHUNK;
    int Mt = rest / NCHUNK;
    int r0 = tile * 16 + (lane >> 2);
    int c0 = ks * 16 + (lane & 3) * 2;
    unsigned hi[4], lo[4];
    #pragma unroll
    for (int e = 0; e < 4; e++) {
        int rr = r0 + (e & 1) * 8;
        int cc = c0 + (e >> 1) * 8;
        unsigned h2 = 0, l2 = 0;
        #pragma unroll
        for (int j = 0; j < 2; j++) {
            int kg = ch * KC + cc + j;
            int ic = kg / 5, kk = kg - 5 * ic;
            int oc = Mt * 128 + rr;
            float w = w1[(oc * 257 + ic) * 5 + kk];
            unsigned short hb = f2h(w);
            unsigned short lb = f2h(w - __half2float(__ushort_as_half(hb)));
            h2 |= ((unsigned)hb) << (16 * j);
            l2 |= ((unsigned)lb) << (16 * j);
        }
        hi[e] = h2; lo[e] = l2;
    }
    g_a1hiF[idx] = make_uint4(hi[0], hi[1], hi[2], hi[3]);
    g_a1loF[idx] = make_uint4(lo[0], lo[1], lo[2], lo[3]);
}
__global__ void prep_w2(const float* __restrict__ w2) {
    int idx = blockIdx.x * blockDim.x + threadIdx.x;
    if (idx >= 2 * FRAG_PER_MT) return;
    int lane = idx & 31;
    int tile = (idx >> 5) & 7;
    int ks   = (idx >> 8) & 3;
    int rest = idx >> 10;
    int ch = rest % NCHUNK;
    int Mt = rest / NCHUNK;
    int r0 = tile * 16 + (lane >> 2);
    int c0 = ks * 16 + (lane & 3) * 2;
    unsigned hi[4], lo[4];
    #pragma unroll
    for (int e = 0; e < 4; e++) {
        int rr = r0 + (e & 1) * 8;
        int cc = c0 + (e >> 1) * 8;
        unsigned h2 = 0, l2 = 0;
        #pragma unroll
        for (int j = 0; j < 2; j++) {
            int kg = ch * KC + cc + j;
            int ic = kg / 5, kk = kg - 5 * ic;
            int oc = Mt * 128 + rr;
            float w = w2[(oc * 256 + ic) * 5 + kk];
            unsigned short hb = f2h(w);
            unsigned short lb = f2h(w - __half2float(__ushort_as_half(hb)));
            h2 |= ((unsigned)hb) << (16 * j);
            l2 |= ((unsigned)lb) << (16 * j);
        }
        hi[e] = h2; lo[e] = l2;
    }
    g_a2hiF[idx] = make_uint4(hi[0], hi[1], hi[2], hi[3]);
    g_a2loF[idx] = make_uint4(lo[0], lo[1], lo[2], lo[3]);
}
__global__ void prep_wdep(const float* __restrict__ w1) {
    int oc = blockIdx.x * blockDim.x + threadIdx.x;
    if (oc >= 512) return;
    float s = 0.f;
    #pragma unroll
    for (int k = 0; k < 5; k++) {
        float w = w1[(oc * 257 + 256) * 5 + k];
        g_wdep[oc * 8 + k] = w;
        s += w;
    }
    g_wdep[oc * 8 + 5] = s;
    g_wdep[oc * 8 + 6] = 0.f;
    g_wdep[oc * 8 + 7] = 0.f;
}

// ---------------- conv1 (stride 2) ----------------
__global__ __launch_bounds__(256, 2) void conv1_mma(
    const int* __restrict__ N0, const float* __restrict__ b1,
    const unsigned short* __restrict__ plane,
    int d, int T_in, int T_out, float dval)
{
    extern __shared__ char smc[];
    const unsigned smb = smem_u32(smc);
    const int tid = threadIdx.x;
    const int b = blockIdx.z, Mtile = blockIdx.y, t0 = blockIdx.x * NT;
    const int lane = tid & 31, q = lane >> 3, r = lane & 7;
    const int w8 = tid >> 5, wmi = w8 >> 1, wni = w8 & 1;

    const int n0v = N0[b];
    const int Ncur = (n0v + (1 << d) - 1) >> d;
    const int Nnew = (n0v + (2 << d) - 1) >> (d + 1);

    // dead-position skip: outputs t >= Nnew are never read downstream
    if (t0 > 0 && t0 >= Nnew) return;

    const unsigned bOff0 = (unsigned)(((q & 1) * 8 + r) * (APAD * 2) + (wni * 32 + (q >> 1) * 8) * 2);
    const unsigned bOff1 = bOff0 + 32;

    float acc[2][4][4];
    #pragma unroll
    for (int mt = 0; mt < 2; mt++)
        #pragma unroll
        for (int nt = 0; nt < 4; nt++)
            #pragma unroll
            for (int e = 0; e < 4; e++) acc[mt][nt][e] = 0.f;

    const int pbase = 2 * (t0 + 2 * lane) - 2;
    unsigned short v[16];

    auto bload = [&](int ch) {
        #pragma unroll
        for (int i = 0; i < 8; i++) {
            int kl = i * 8 + w8;
            int kg = ch * KC + kl;
            int ic = kg / 5, kk = kg - 5 * ic;
            unsigned base = (unsigned)(b * NHC + ic) * (unsigned)T_in;
            int p0 = pbase + kk;
            int p1 = p0 + 2;
            v[2 * i]     = (p0 >= 0 && p0 < Ncur) ? plane[base + p0] : (unsigned short)0;
            v[2 * i + 1] = (p1 >= 0 && p1 < Ncur) ? plane[base + p1] : (unsigned short)0;
        }
    };
    auto bstore = [&](int st) {
        unsigned* bh = (unsigned*)(smc + st * SM_STAGE);
        #pragma unroll
        for (int i = 0; i < 8; i++) {
            int kl = i * 8 + w8;
            int so = kl * (APAD / 2) + lane;
            bh[so] = (unsigned)v[2 * i] | ((unsigned)v[2 * i + 1] << 16);
        }
    };

    const uint4* Ah0 = g_a1hiF + (size_t)Mtile * FRAG_PER_MT;
    const uint4* Al0 = g_a1loF + (size_t)Mtile * FRAG_PER_MT;
    const int lbase = wmi * 2 * 32 + lane;

    // A-fragment register pipeline: current step's 4 fragments
    uint4 aH0, aH1, aL0, aL1;
    {
        const int f0 = lbase;
        aH0 = Ah0[f0]; aH1 = Ah0[f0 + 32];
        aL0 = Al0[f0]; aL1 = Al0[f0 + 32];
    }

    bload(0);
    for (int ch = 0; ch < NCHUNK; ch++) {
        const int st = ch & 1;
        bstore(st);
        __syncthreads();
        if (ch + 1 < NCHUNK) bload(ch + 1);
        const unsigned bbase = smb + st * SM_STAGE;
        #pragma unroll
        for (int ks = 0; ks < 4; ks++) {
            // prefetch A fragments for next step (clamped at the last step)
            const int un = ch * 4 + ks + 1;
            const int fn = (un < 80 ? un : 79) * 8 * 32 + lbase;
            uint4 nH0 = Ah0[fn], nH1 = Ah0[fn + 32];
            uint4 nL0 = Al0[fn], nL1 = Al0[fn + 32];

            const unsigned kr = (unsigned)(ks * 16 * (APAD * 2));
            unsigned bhf[4][2], f[4];
            ldm4t(f, bbase + bOff0 + kr);
            bhf[0][0] = f[0]; bhf[0][1] = f[1]; bhf[1][0] = f[2]; bhf[1][1] = f[3];
            ldm4t(f, bbase + bOff1 + kr);
            bhf[2][0] = f[0]; bhf[2][1] = f[1]; bhf[3][0] = f[2]; bhf[3][1] = f[3];

            const unsigned* Ahc[2] = {(const unsigned*)&aH0, (const unsigned*)&aH1};
            const unsigned* Alc[2] = {(const unsigned*)&aL0, (const unsigned*)&aL1};
            #pragma unroll
            for (int mt = 0; mt < 2; mt++) {
                #pragma unroll
                for (int nt = 0; nt < 4; nt++) {
                    mma16816(acc[mt][nt], Ahc[mt], bhf[nt]);
                    mma16816(acc[mt][nt], Alc[mt], bhf[nt]);
                }
            }
            aH0 = nH0; aH1 = nH1; aL0 = nL0; aL1 = nL1;
        }
    }

    // epilogue
    const int crow = lane >> 2, ccol = (lane & 3) * 2;
    const bool dep = (dval != 0.f);
    #pragma unroll
    for (int mt = 0; mt < 2; mt++) {
        #pragma unroll
        for (int rh = 0; rh < 2; rh++) {
            const int oc = Mtile * 128 + wmi * 32 + mt * 16 + rh * 8 + crow;
            const float bias = b1[oc];
            float wd[5], sfull = 0.f;
            if (dep) {
                float4 wA = *(const float4*)&g_wdep[oc * 8];
                float2 wB = *(const float2*)&g_wdep[oc * 8 + 4];
                wd[0] = wA.x; wd[1] = wA.y; wd[2] = wA.z; wd[3] = wA.w; wd[4] = wB.x;
                sfull = wB.y;
            }
            auto dcor = [&](int t) -> float {
                if (t >= 1 && 2 * t + 2 < Ncur) return sfull;
                float s = 0.f;
                #pragma unroll
                for (int k = 0; k < 5; k++) {
                    int p = 2 * t + k - 2;
                    if (p >= 0 && p < Ncur) s += wd[k];
                }
                return s;
            };
            #pragma unroll
            for (int nt = 0; nt < 4; nt++) {
                const int tg = t0 + wni * 32 + nt * 8 + ccol;
                float c0v = acc[mt][nt][rh * 2 + 0] + bias;
                float c1v = acc[mt][nt][rh * 2 + 1] + bias;
                if (dep) {
                    c0v += dval * dcor(tg);
                    c1v += dval * dcor(tg + 1);
                }
                if (Mtile < 2) {
                    size_t off = (size_t)(b * NHC + oc) * T_out + tg;
                    if (tg + 1 < T_out)      *(float2*)&g_bufL[off] = make_float2(c0v, c1v);
                    else if (tg < T_out)     g_bufL[off] = c0v;
                } else {
                    float r0v = fmaxf(c0v, 0.f); if (tg     >= Nnew) r0v = 0.f;
                    float r1v = fmaxf(c1v, 0.f); if (tg + 1 >= Nnew) r1v = 0.f;
                    size_t off = (size_t)(b * NHC + oc - 256) * T_out + tg;
                    if (tg + 1 < T_out)
                        *(unsigned*)&g_rplane[off] = (unsigned)f2h(r0v) | ((unsigned)f2h(r1v) << 16);
                    else if (tg < T_out)
                        g_rplane[off] = f2h(r0v);
                }
            }
        }
    }
}

// ---------------- conv2 (stride 1) ----------------
__global__ __launch_bounds__(256, 2) void conv2_mma(
    const int* __restrict__ N0, const float* __restrict__ b2,
    int d, int T_out)
{
    extern __shared__ char smc[];
    const unsigned smb = smem_u32(smc);
    const int tid = threadIdx.x;
    const int b = blockIdx.z, Mtile = blockIdx.y, t0 = blockIdx.x * NT;
    const int lane = tid & 31, q = lane >> 3, r = lane & 7;
    const int w8 = tid >> 5, wmi = w8 >> 1, wni = w8 & 1;
    unsigned short* hout = (d & 1) ? g_hplane1 : g_hplane0;

    const int n0v = N0[b];
    const int Nnew = (n0v + (2 << d) - 1) >> (d + 1);

    // dead-position skip (see conv1)
    if (t0 > 0 && t0 >= Nnew) return;

    const unsigned bOff0 = (unsigned)(((q & 1) * 8 + r) * (APAD * 2) + (wni * 32 + (q >> 1) * 8) * 2);
    const unsigned bOff1 = bOff0 + 32;

    float acc[2][4][4];
    #pragma unroll
    for (int mt = 0; mt < 2; mt++)
        #pragma unroll
        for (int nt = 0; nt < 4; nt++)
            #pragma unroll
            for (int e = 0; e < 4; e++) acc[mt][nt][e] = 0.f;

    const int pbase = t0 + 2 * lane - 2;
    unsigned short v[16];

    auto bload = [&](int ch) {
        #pragma unroll
        for (int i = 0; i < 8; i++) {
            int kl = i * 8 + w8;
            int kg = ch * KC + kl;
            int ic = kg / 5, kk = kg - 5 * ic;
            unsigned base = (unsigned)(b * NHC + ic) * (unsigned)T_out;
            int p0 = pbase + kk;
            int p1 = p0 + 1;
            v[2 * i]     = (p0 >= 0 && p0 < Nnew) ? g_rplane[base + p0] : (unsigned short)0;
            v[2 * i + 1] = (p1 >= 0 && p1 < Nnew) ? g_rplane[base + p1] : (unsigned short)0;
        }
    };
    auto bstore = [&](int st) {
        unsigned* bh = (unsigned*)(smc + st * SM_STAGE);
        #pragma unroll
        for (int i = 0; i < 8; i++) {
            int kl = i * 8 + w8;
            int so = kl * (APAD / 2) + lane;
            bh[so] = (unsigned)v[2 * i] | ((unsigned)v[2 * i + 1] << 16);
        }
    };

    const uint4* Ah0 = g_a2hiF + (size_t)Mtile * FRAG_PER_MT;
    const uint4* Al0 = g_a2loF + (size_t)Mtile * FRAG_PER_MT;
    const int lbase = wmi * 2 * 32 + lane;

    uint4 aH0, aH1, aL0, aL1;
    {
        const int f0 = lbase;
        aH0 = Ah0[f0]; aH1 = Ah0[f0 + 32];
        aL0 = Al0[f0]; aL1 = Al0[f0 + 32];
    }

    bload(0);
    for (int ch = 0; ch < NCHUNK; ch++) {
        const int st = ch & 1;
        bstore(st);
        __syncthreads();
        if (ch + 1 < NCHUNK) bload(ch + 1);
        const unsigned bbase = smb + st * SM_STAGE;
        #pragma unroll
        for (int ks = 0; ks < 4; ks++) {
            const int un = ch * 4 + ks + 1;
            const int fn = (un < 80 ? un : 79) * 8 * 32 + lbase;
            uint4 nH0 = Ah0[fn], nH1 = Ah0[fn + 32];
            uint4 nL0 = Al0[fn], nL1 = Al0[fn + 32];

            const unsigned kr = (unsigned)(ks * 16 * (APAD * 2));
            unsigned bhf[4][2], f[4];
            ldm4t(f, bbase + bOff0 + kr);
            bhf[0][0] = f[0]; bhf[0][1] = f[1]; bhf[1][0] = f[2]; bhf[1][1] = f[3];
            ldm4t(f, bbase + bOff1 + kr);
            bhf[2][0] = f[0]; bhf[2][1] = f[1]; bhf[3][0] = f[2]; bhf[3][1] = f[3];

            const unsigned* Ahc[2] = {(const unsigned*)&aH0, (const unsigned*)&aH1};
            const unsigned* Alc[2] = {(const unsigned*)&aL0, (const unsigned*)&aL1};
            #pragma unroll
            for (int mt = 0; mt < 2; mt++) {
                #pragma unroll
                for (int nt = 0; nt < 4; nt++) {
                    mma16816(acc[mt][nt], Ahc[mt], bhf[nt]);
                    mma16816(acc[mt][nt], Alc[mt], bhf[nt]);
                }
            }
            aH0 = nH0; aH1 = nH1; aL0 = nL0; aL1 = nL1;
        }
    }

    const int crow = lane >> 2, ccol = (lane & 3) * 2;
    const int fd = finish_depth(n0v);
    #pragma unroll
    for (int mt = 0; mt < 2; mt++) {
        #pragma unroll
        for (int rh = 0; rh < 2; rh++) {
            const int oc = Mtile * 128 + wmi * 32 + mt * 16 + rh * 8 + crow;
            const float bias = b2[oc];
            #pragma unroll
            for (int nt = 0; nt < 4; nt++) {
                const int tg = t0 + wni * 32 + nt * 8 + ccol;
                const float c0v = acc[mt][nt][rh * 2 + 0] + bias;
                const float c1v = acc[mt][nt][rh * 2 + 1] + bias;
                size_t off = (size_t)(b * NHC + oc) * T_out + tg;
                if (tg + 1 < T_out) {
                    float2 L = *(const float2*)&g_bufL[off];
                    float v0 = fmaxf(c0v + L.x, 0.f);
                    float v1 = fmaxf(c1v + L.y, 0.f);
                    *(unsigned*)&hout[off] = (unsigned)f2h(v0) | ((unsigned)f2h(v1) << 16);
                    if (tg == 0 && fd == d) g_captured[b * NHC + oc] = v0;
                } else if (tg < T_out) {
                    float v0 = fmaxf(c0v + g_bufL[off], 0.f);
                    hout[off] = f2h(v0);
                    if (tg == 0 && fd == d) g_captured[b * NHC + oc] = v0;
                }
            }
        }
    }
}

// ---------------- finalize ----------------
__global__ void finalize_kernel(const int* __restrict__ N0, float* __restrict__ out)
{
    __shared__ int order[BATCH];
    if (threadIdx.x == 0) {
        int fd[BATCH];
        int cnt[13];
        for (int i = 0; i < 13; i++) cnt[i] = 0;
        for (int bb = 0; bb < BATCH; bb++) {
            fd[bb] = finish_depth(N0[bb]);
            cnt[fd[bb]]++;
        }
        int pos[13];
        int run = 0;
        for (int i = 0; i < 13; i++) { pos[i] = run; run += cnt[i]; }
        for (int bb = 0; bb < BATCH; bb++) order[pos[fd[bb]]++] = bb;
    }
    __syncthreads();
    for (int i = threadIdx.x; i < BATCH * NHC; i += blockDim.x) {
        int row = i >> 8, c = i & 255;
        out[i] = g_captured[order[row] * NHC + c];
    }
}

// ---------------- launch ----------------
extern "C" void kernel_launch(void* const* d_in, const int* in_sizes, int n_in,
                              void* d_out, int out_size)
{
    const float* h  = (const float*)d_in[0];
    const int*   N0 = (const int*)d_in[1];
    const float* w1 = (const float*)d_in[2];
    const float* b1 = (const float*)d_in[3];
    const float* w2 = (const float*)d_in[4];
    const float* b2 = (const float*)d_in[5];

    cudaFuncSetAttribute(conv1_mma, cudaFuncAttributeMaxDynamicSharedMemorySize, SM_DYN);
    cudaFuncSetAttribute(conv2_mma, cudaFuncAttributeMaxDynamicSharedMemorySize, SM_DYN);

    {
        long long tot = (long long)BATCH * NHC * TMAX;
        prep_input<<<(int)((tot + 255) / 256), 256>>>(h);
        prep_w1<<<(4 * FRAG_PER_MT + 255) / 256, 256>>>(w1);
        prep_w2<<<(2 * FRAG_PER_MT + 255) / 256, 256>>>(w2);
        prep_wdep<<<2, 256>>>(w1);
    }

    unsigned short* hp0; unsigned short* hp1; unsigned short* inp;
    cudaGetSymbolAddress((void**)&hp0, g_hplane0);
    cudaGetSymbolAddress((void**)&hp1, g_hplane1);
    cudaGetSymbolAddress((void**)&inp, g_inplane);

    for (int d = 0; d < 12; d++) {
        int T_in  = TMAX >> d;
        int T_out = T_in >> 1;
        int tiles = (T_out + NT - 1) / NT;
        float dval = (float)log1p((double)d);
        const unsigned short* plane = (d == 0) ? inp : (((d - 1) & 1) ? hp1 : hp0);
        conv1_mma<<<dim3(tiles, 4, BATCH), 256, SM_DYN>>>(N0, b1, plane, d, T_in, T_out, dval);
        conv2_mma<<<dim3(tiles, 2, BATCH), 256, SM_DYN>>>(N0, b2, d, T_out);
    }
    finalize_kernel<<<1, 256>>>(N0, (float*)d_out);
}